// round 11
// baseline (speedup 1.0000x reference)
#include <cuda_runtime.h>
#include <cuda_bf16.h>
#include <cstdint>

// ---------------------------------------------------------------------------
// RNN_MultiRegional_SAC — persistent bf16 mma.sync kernel, take 3.
// h = relu(0.9 h + 0.1 (h @ W^T + drive)), 512 steps, B=32, 3H=3072.
// W_rec: 5 nonzero 1024x1024 blocks bf16: [W00=-fixed, W02, W10, W21, W22]
// 160 perfectly-balanced blocks (8 K128-tiles each), all co-resident (2/SM max):
//   bid 0..63:   str  pair=bid>>1, khalf=bid&1 (W00 | W02)
//   bid 64..127: m1   pair=32+((bid-64)>>1)    (W21 | W22)
//   bid 128..159: thal (W10), no pairing
// W (64KB) staged to smem ONCE; per step only h tiles stream (5-buffer ring,
// cp.async.bulk + parity mbarriers). Pair halves combine via gmem partials +
// per-(t,pair) atomic flag (second arriver finishes; no spinning). One light
// grid barrier per step. fp32 master h; bf16 mma operands.
// Output (float32): [mean 32*512][std 32*512][hn_last 32*3072][rnn 32*512*3072]
// ---------------------------------------------------------------------------

#define Hh   1024
#define H3   3072
#define Bz   32
#define Tz   512
#define NEXC 717
#define HH   (Hh*Hh)
#define NBLK 160
#define SMEM_BYTES (65536 + 5 * 8192)   // W 64KB + h ring 40KB = 104KB

// Packed, per-block-contiguous, pre-swizzled W tiles: [bid 160][kt 8][4096 bf16]
__device__ __align__(256) __nv_bfloat16 g_Wp[160u * 8u * 4096u];   // 10 MB
__device__ __align__(256) float         g_hf[2][Bz * H3];          // fp32 master h [b][n]
// bf16 operand h, tiled+swizzled: 24 tiles of 4096 elems; tile tk holds k in
// [tk*128,(tk+1)*128): elem off = b*128 + ((((k>>3)&15)^(b&7))<<3) + (k&7)
__device__ __align__(256) __nv_bfloat16 g_hb[2][24 * 4096];
__device__ __align__(256) float         g_part[64 * 2 * 1024];     // [pair][khalf][n32*b32]
__device__ int g_flag[Tz * 64];                                     // per-(step,pair) arrivals
__device__ unsigned g_cnt;                                          // barrier counter (self-reset)
__device__ unsigned g_gen;                                          // barrier generation

// ---------------- helpers ----------------
__device__ __forceinline__ unsigned smem_u32(const void* p) {
    return (unsigned)__cvta_generic_to_shared(p);
}
__device__ __forceinline__ void bulk_cp8k(unsigned dstS, const void* srcG, unsigned mbarS) {
    asm volatile("cp.async.bulk.shared::cta.global.mbarrier::complete_tx::bytes [%0], [%1], %2, [%3];"
                 :: "r"(dstS), "l"(srcG), "n"(8192), "r"(mbarS) : "memory");
}
__device__ __forceinline__ void bulk_cp64k(unsigned dstS, const void* srcG, unsigned mbarS) {
    asm volatile("cp.async.bulk.shared::cta.global.mbarrier::complete_tx::bytes [%0], [%1], %2, [%3];"
                 :: "r"(dstS), "l"(srcG), "n"(65536), "r"(mbarS) : "memory");
}
__device__ __forceinline__ void mbar_init(unsigned mbarS) {
    asm volatile("mbarrier.init.shared.b64 [%0], 1;" :: "r"(mbarS) : "memory");
}
__device__ __forceinline__ void mbar_expect(unsigned mbarS, unsigned bytes) {
    asm volatile("mbarrier.arrive.expect_tx.shared.b64 _, [%0], %1;" :: "r"(mbarS), "r"(bytes) : "memory");
}
__device__ __forceinline__ void mbar_wait(unsigned mbarS, unsigned parity) {
    asm volatile(
        "{\n\t.reg .pred P;\n"
        "W_%=:\n\t"
        "mbarrier.try_wait.parity.acquire.cta.shared::cta.b64 P, [%0], %1, 0x989680;\n\t"
        "@P bra D_%=;\n\t"
        "bra W_%=;\n"
        "D_%=:\n\t}"
        :: "r"(mbarS), "r"(parity) : "memory");
}

// ---------------- prep: pack W into per-block swizzled tiles + zero flags ------
__global__ void prep_pack(const float* __restrict__ w_str2thal,
                          const float* __restrict__ w_m12m1,
                          const float* __restrict__ w_m12str,
                          const float* __restrict__ w_thal2m1,
                          const float* __restrict__ fixedw) {
    int e = blockIdx.x * blockDim.x + threadIdx.x;
    if (e >= 160 * 8 * 4096) return;
    if (e < Tz * 64) g_flag[e] = 0;

    int bid = e >> 15;              // /32768
    int rem = e & 32767;
    int kt  = rem >> 12;
    int wi  = rem & 4095;
    int row = wi >> 7;              // n within 32-strip
    int chunkS = (wi >> 3) & 15;
    int chunk  = chunkS ^ (row & 7);
    int kl  = (chunk << 3) | (wi & 7);    // k within 128-tile

    int n0loc, region;
    if (bid < 64)       { int strip = bid >> 1;        n0loc = strip * 32; region = (bid & 1) ? 1 : 0; }
    else if (bid < 128) { int strip = (bid - 64) >> 1; n0loc = strip * 32; region = (bid & 1) ? 4 : 3; }
    else                { n0loc = (bid - 128) * 32;    region = 2; }

    int n = n0loc + row;
    int k = (kt << 7) + kl;
    int src = n * Hh + k;

    float val;
    if (region == 0)      val = -fixedw[src];
    else if (region == 1) { float v = fminf(fmaxf(w_m12str[src], 1e-10f), 1.0f);  val = (k < NEXC) ? v : 0.0f; }
    else if (region == 2) { float v = fminf(fmaxf(w_str2thal[src], 1e-10f), 1.0f); val = (k < (Hh/2)) ? v : -v; }
    else if (region == 3) val = fminf(fmaxf(w_thal2m1[src], 1e-10f), 1.0f);
    else                  { float v = fminf(fmaxf(w_m12m1[src], 1e-10f), 1.0f);   val = (k < NEXC) ? v : -v; }

    g_Wp[e] = __float2bfloat16(val);
}

// ---------------- init: hn ([b][n]) -> h masters --------------------------------
__global__ void init_kernel(const float* __restrict__ hn) {
    int idx = blockIdx.x * blockDim.x + threadIdx.x;
    if (idx >= Bz * H3) return;
    int b = idx / H3, n = idx - b * H3;
    float v = hn[idx];
    g_hf[0][idx] = v;
    int off = (n >> 7) * 4096 + b * 128 + ((((n >> 3) & 15) ^ (b & 7)) << 3) + (n & 7);
    g_hb[0][off] = __float2bfloat16(v);
}

// ---------------- persistent tensor-core kernel ----------------------------------
// 256 threads = 8 warps; warp = (bt = w&1: batch half, nh = w>>1: n-octet).
// smem: W 64KB (resident all steps) + h ring 5 x 8KB.
__global__ void __launch_bounds__(256, 2) rnn_persist(const float* __restrict__ inp,
                                                      const float* __restrict__ iw,
                                                      float* __restrict__ rnn) {
    extern __shared__ __align__(256) unsigned char smem[];   // [0,64K): W, [64K,104K): h ring
    __shared__ __align__(8) unsigned long long mbar[9];       // 0..7 h tiles, 8 = W
    __shared__ int swin;

    const int tx   = threadIdx.x;
    const int bid  = blockIdx.x;
    const int wid  = tx >> 5;
    const int lane = tx & 31;

    // ---- block decode ----
    int n0, pair, khalf, htile0;
    bool thal = false;
    if (bid < 64)       { int s = bid >> 1;        khalf = bid & 1; n0 = s * 32;        pair = s;      htile0 = khalf ? 16 : 0; }
    else if (bid < 128) { int s = (bid - 64) >> 1; khalf = bid & 1; n0 = 2048 + s * 32; pair = 32 + s; htile0 = khalf ? 16 : 8; }
    else                { int s = bid - 128;       khalf = 0;       n0 = 1024 + s * 32; pair = 0;      htile0 = 0; thal = true; }

    const unsigned sBase   = smem_u32(smem);
    const unsigned hRegion = sBase + 65536;
    const unsigned mBase   = smem_u32(mbar);

    // ---- one-time prologue: barriers + resident W ----
    if (tx == 0) {
#pragma unroll
        for (int i = 0; i < 9; i++) mbar_init(mBase + i * 8);
    }
    __syncthreads();
    if (tx == 0) {
        mbar_expect(mBase + 8 * 8, 65536);
        bulk_cp64k(sBase, g_Wp + (size_t)bid * 32768, mBase + 8 * 8);
    }
    mbar_wait(mBase + 8 * 8, 0);
    __syncthreads();

    // ---- ldmatrix lane addressing (same swizzle as packed tiles) ----
    const int bt = wid & 1, nh = wid >> 1;
    const int am = lane >> 3;
    const int arow = bt * 16 + (am & 1) * 8 + (lane & 7);   // A row (batch)
    const int qa   = am >> 1;
    const int sa   = arow & 7;
    const int brow = nh * 8 + (lane & 7);                   // B row (n)
    const int grp  = lane >> 3;
    const int sb   = brow & 7;
    const unsigned habase = hRegion + arow * 256;
    const unsigned wbbase = sBase + brow * 256;

    // ---- epilogue constants (hoisted) ----
    const int g  = lane >> 2, tg = lane & 3;
    const int pn = nh * 8 + 2 * tg;
    const int pb = bt * 16 + g;
    const int ncol = n0 + pn;
    float iwv[2][4];
#pragma unroll
    for (int j = 0; j < 2; j++)
#pragma unroll
        for (int i = 0; i < 4; i++) iwv[j][i] = iw[i * H3 + ncol + j];

    unsigned tgt;
    asm volatile("ld.volatile.global.u32 %0, [%1];" : "=r"(tgt) : "l"(&g_gen));

    // =================== time loop ===================
#pragma unroll 1
    for (int t = 0; t < Tz; t++) {
        const int cur = t & 1, nxt = cur ^ 1;
        const unsigned par = (unsigned)(t & 1);
        const __nv_bfloat16* __restrict__ hsrc = g_hb[cur] + htile0 * 4096;

        // stage h tiles 0..4 into ring buffers 0..4
        if (tx == 0) {
#pragma unroll
            for (int i = 0; i < 5; i++) {
                unsigned mb = mBase + i * 8;
                mbar_expect(mb, 8192);
                bulk_cp8k(hRegion + i * 8192, hsrc + i * 4096, mb);
            }
        }

        float d[2][4];
#pragma unroll
        for (int e = 0; e < 2; e++)
#pragma unroll
            for (int j = 0; j < 4; j++) d[e][j] = 0.f;

#pragma unroll 1
        for (int kt = 0; kt < 8; kt++) {
            mbar_wait(mBase + kt * 8, par);

            const unsigned ha = habase + (kt % 5) * 8192;
            const unsigned wa = wbbase + kt * 8192;
#pragma unroll
            for (int kp = 0; kp < 4; kp++) {
                unsigned b0, b1, b2, b3;
                asm volatile("ldmatrix.sync.aligned.m8n8.x4.shared.b16 {%0,%1,%2,%3}, [%4];"
                             : "=r"(b0), "=r"(b1), "=r"(b2), "=r"(b3)
                             : "r"(wa + (((4 * kp + grp) ^ sb) << 4)));
                unsigned a0, a1, a2, a3;
                asm volatile("ldmatrix.sync.aligned.m8n8.x4.shared.b16 {%0,%1,%2,%3}, [%4];"
                             : "=r"(a0), "=r"(a1), "=r"(a2), "=r"(a3)
                             : "r"(ha + (((4 * kp + qa) ^ sa) << 4)));
                asm volatile("mma.sync.aligned.m16n8k16.row.col.f32.bf16.bf16.f32 "
                             "{%0,%1,%2,%3}, {%4,%5,%6,%7}, {%8,%9}, {%0,%1,%2,%3};"
                             : "+f"(d[0][0]), "+f"(d[0][1]), "+f"(d[0][2]), "+f"(d[0][3])
                             : "r"(a0), "r"(a1), "r"(a2), "r"(a3), "r"(b0), "r"(b1));
                unsigned c0, c1, c2, c3;
                asm volatile("ldmatrix.sync.aligned.m8n8.x4.shared.b16 {%0,%1,%2,%3}, [%4];"
                             : "=r"(c0), "=r"(c1), "=r"(c2), "=r"(c3)
                             : "r"(ha + (((4 * kp + 2 + qa) ^ sa) << 4)));
                asm volatile("mma.sync.aligned.m16n8k16.row.col.f32.bf16.bf16.f32 "
                             "{%0,%1,%2,%3}, {%4,%5,%6,%7}, {%8,%9}, {%0,%1,%2,%3};"
                             : "+f"(d[1][0]), "+f"(d[1][1]), "+f"(d[1][2]), "+f"(d[1][3])
                             : "r"(c0), "r"(c1), "r"(c2), "r"(c3), "r"(b2), "r"(b3));
            }

            // refill ring buffer (kt%5) with tile kt+5 once all warps consumed kt
            if (kt < 3) {
                __syncthreads();
                if (tx == 0) {
                    int i = kt + 5;
                    unsigned mb = mBase + i * 8;
                    mbar_expect(mb, 8192);
                    bulk_cp8k(hRegion + (i % 5) * 8192, hsrc + i * 4096, mb);
                }
            }
        }

        float ds[4];
#pragma unroll
        for (int j = 0; j < 4; j++) ds[j] = d[0][j] + d[1][j];

        // ---- pair combine: write partials, second arriver finishes ----
        bool do_epi = true;
        if (!thal) {
            float* pp = g_part + (pair * 2 + khalf) * 1024;
#pragma unroll
            for (int half = 0; half < 2; half++)
#pragma unroll
                for (int j = 0; j < 2; j++)
                    pp[(pn + j) * 32 + pb + half * 8] = ds[half * 2 + j];
            __threadfence();
            __syncthreads();
            if (tx == 0) swin = atomicAdd(&g_flag[t * 64 + pair], 1);
            __syncthreads();
            if (swin == 0) {
                do_epi = false;              // first arriver: partner finishes
            } else {
                __threadfence();             // acquire
                const float* qq = g_part + (pair * 2 + (khalf ^ 1)) * 1024;
#pragma unroll
                for (int half = 0; half < 2; half++)
#pragma unroll
                    for (int j = 0; j < 2; j++)
                        ds[half * 2 + j] += __ldcg(&qq[(pn + j) * 32 + pb + half * 8]);
            }
        }

        // ---- epilogue: drive + relu; write fp32 master, tiled bf16 operand, rnn ----
        if (do_epi) {
            float* __restrict__ hfn = g_hf[nxt];
            __nv_bfloat16* __restrict__ hbn = g_hb[nxt];
            const float* __restrict__ hfc = g_hf[cur];

#pragma unroll
            for (int half = 0; half < 2; half++) {
                int b = pb + half * 8;
                float4 iv = ((const float4*)inp)[b * Tz + t];
                float v2[2];
#pragma unroll
                for (int j = 0; j < 2; j++) {
                    int n = ncol + j;
                    float drv = iv.x * iwv[j][0] + iv.y * iwv[j][1]
                              + iv.z * iwv[j][2] + iv.w * iwv[j][3];
                    float hp = hfc[b * H3 + n];
                    float v = fmaxf(0.9f * hp + 0.1f * (ds[half * 2 + j] + drv), 0.0f);
                    v2[j] = v;
                    hfn[b * H3 + n] = v;
                    rnn[((size_t)(b * Tz + t)) * H3 + n] = v;
                }
                int n = ncol;
                int off = (n >> 7) * 4096 + b * 128 + ((((n >> 3) & 15) ^ (b & 7)) << 3) + (n & 7);
                __nv_bfloat162 pk;
                pk.x = __float2bfloat16(v2[0]);
                pk.y = __float2bfloat16(v2[1]);
                *(__nv_bfloat162*)&hbn[off] = pk;
            }
        }

        // ---- grid barrier ----
        __syncthreads();
        if (tx == 0) {
            __threadfence();
            ++tgt;
            if (atomicAdd(&g_cnt, 1u) == NBLK - 1) {
                g_cnt = 0;
                __threadfence();
                atomicExch(&g_gen, tgt);
            } else {
                unsigned curgen;
                do {
                    __nanosleep(64);
                    asm volatile("ld.volatile.global.u32 %0, [%1];" : "=r"(curgen) : "l"(&g_gen));
                } while ((int)(curgen - tgt) < 0);
                __threadfence();
            }
        } else { ++tgt; }
        __syncthreads();
    }
}

// ---------------- heads: mean/std over masked (m1) region ----------------------
__global__ void head_kernel(const float* __restrict__ rnn,
                            const float* __restrict__ mean_w, const float* __restrict__ mean_b,
                            const float* __restrict__ std_w,  const float* __restrict__ std_b,
                            float* __restrict__ mean_out, float* __restrict__ std_out) {
    int warp = blockIdx.x * 8 + (threadIdx.x >> 5);   // = b*512 + t
    int lane = threadIdx.x & 31;
    const float* row = rnn + (size_t)warp * H3 + 2048;
    float sm = 0.0f, ss = 0.0f;
#pragma unroll 8
    for (int i = lane; i < Hh; i += 32) {
        float v = row[i];
        sm += v * mean_w[2048 + i];
        ss += v * std_w[2048 + i];
    }
#pragma unroll
    for (int off = 16; off; off >>= 1) {
        sm += __shfl_down_sync(0xFFFFFFFFu, sm, off);
        ss += __shfl_down_sync(0xFFFFFFFFu, ss, off);
    }
    if (lane == 0) {
        mean_out[warp] = sm + mean_b[0];
        float s = ss + std_b[0];
        std_out[warp] = fminf(fmaxf(s, -5.0f), 10.0f);
    }
}

// ---------------- hn_last copy --------------------------------------------------
__global__ void hn_kernel(const float* __restrict__ rnn, float* __restrict__ hn_out) {
    int idx = blockIdx.x * blockDim.x + threadIdx.x;
    if (idx >= Bz * H3) return;
    int b = idx / H3, n = idx - b * H3;
    hn_out[idx] = rnn[((size_t)(b * Tz + (Tz - 1))) * H3 + n];
}

// ---------------- launch ---------------------------------------------------------
extern "C" void kernel_launch(void* const* d_in, const int* in_sizes, int n_in,
                              void* d_out, int out_size) {
    const float* inp        = (const float*)d_in[0];   // [32,512,4]
    const float* hn         = (const float*)d_in[1];   // [1,32,3072]
    // d_in[2] = w_str2str (unused: its mask is all-zeros in the reference)
    const float* w_str2thal = (const float*)d_in[3];
    const float* w_m12m1    = (const float*)d_in[4];
    const float* w_m12str   = (const float*)d_in[5];
    const float* w_thal2m1  = (const float*)d_in[6];
    const float* fixedw     = (const float*)d_in[7];
    const float* inp_weight = (const float*)d_in[8];   // [4,3072]
    const float* mean_w     = (const float*)d_in[9];   // [1,3072]
    const float* mean_b     = (const float*)d_in[10];  // [1]
    const float* std_w      = (const float*)d_in[11];
    const float* std_b      = (const float*)d_in[12];
    // d_in[13] = sampling flag

    float* out      = (float*)d_out;
    float* mean_out = out;                         // 32*512
    float* std_out  = out + 16384;                 // 32*512
    float* hn_out   = out + 32768;                 // 32*3072
    float* rnn      = out + 131072;                // 32*512*3072

    cudaFuncSetAttribute(rnn_persist, cudaFuncAttributeMaxDynamicSharedMemorySize, SMEM_BYTES);

    prep_pack<<<(160 * 8 * 4096 + 255) / 256, 256>>>(w_str2thal, w_m12m1, w_m12str, w_thal2m1, fixedw);
    init_kernel<<<(Bz * H3 + 255) / 256, 256>>>(hn);

    rnn_persist<<<NBLK, 256, SMEM_BYTES>>>(inp, inp_weight, rnn);

    head_kernel<<<2048, 256>>>(rnn, mean_w, mean_b, std_w, std_b, mean_out, std_out);
    hn_kernel<<<(Bz * H3 + 255) / 256, 256>>>(rnn, hn_out);
}

// round 12
// speedup vs baseline: 1.1841x; 1.1841x over previous
#include <cuda_runtime.h>
#include <cuda_bf16.h>
#include <cstdint>

// ---------------------------------------------------------------------------
// RNN_MultiRegional_SAC — persistent bf16 mma.sync, 80 blocks x 512 threads.
// h = relu(0.9 h + 0.1 (h @ W^T + drive)), 512 steps, B=32, 3H=3072.
// W_rec: 5 nonzero 1024x1024 blocks bf16: [W00=-fixed, W02, W10, W21, W22]
// 80 perfectly-balanced blocks, ONE per SM, W resident in smem (128KB):
//   bid 0..31:  str strip 32n: ks0 warps W00 (h[0:1024]), ks1 warps W02 (h[2048:3072])
//   bid 32..63: m1  strip 32n: ks0 W21 (h[1024:2048]),    ks1 W22 (h[2048:3072])
//   bid 64..79: thal strip 64n: all warps W10 (h[0:1024]), no K-split
// 16 warps/block: (bt = batch half, nh = n-octet, ks = K-half). K-split halves
// combine IN SMEM (8KB + 1 syncthreads) — no gmem partials, no atomics.
// h streams via cp.async.bulk into two 5-slot rings; one grid barrier/step.
// fp32 master h; bf16 mma operands.
// Output (float32): [mean 32*512][std 32*512][hn_last 32*3072][rnn 32*512*3072]
// ---------------------------------------------------------------------------

#define Hh   1024
#define H3   3072
#define Bz   32
#define Tz   512
#define NEXC 717
#define HH   (Hh*Hh)
#define NBLK 80

#define OFF_HA  131072u
#define OFF_HB  172032u
#define OFF_CB  212992u
#define SMEM_BYTES 221184   // W 128K + ringA 40K + ringB 40K + comb 8K

// Packed, per-block-contiguous, pre-swizzled W: [bid 80][kt 16][4096 bf16] = 10.5MB
__device__ __align__(256) __nv_bfloat16 g_Wp[80u * 16u * 4096u];
__device__ __align__(256) float         g_hf[2][Bz * H3];   // fp32 master h [b][n]
// bf16 operand h, tiled+swizzled: 24 tiles of 4096; tile tk holds k in
// [tk*128,(tk+1)*128): elem off = b*128 + ((((k>>3)&15)^(b&7))<<3) + (k&7)
__device__ __align__(256) __nv_bfloat16 g_hb[2][24 * 4096];
__device__ unsigned g_cnt;                                   // barrier counter (self-reset)
__device__ unsigned g_gen;                                   // barrier generation

// ---------------- helpers ----------------
__device__ __forceinline__ unsigned smem_u32(const void* p) {
    return (unsigned)__cvta_generic_to_shared(p);
}
__device__ __forceinline__ void bulk_cp(unsigned dstS, const void* srcG, unsigned bytes, unsigned mbarS) {
    asm volatile("cp.async.bulk.shared::cta.global.mbarrier::complete_tx::bytes [%0], [%1], %2, [%3];"
                 :: "r"(dstS), "l"(srcG), "r"(bytes), "r"(mbarS) : "memory");
}
__device__ __forceinline__ void mbar_init(unsigned mbarS) {
    asm volatile("mbarrier.init.shared.b64 [%0], 1;" :: "r"(mbarS) : "memory");
}
__device__ __forceinline__ void mbar_expect(unsigned mbarS, unsigned bytes) {
    asm volatile("mbarrier.arrive.expect_tx.shared.b64 _, [%0], %1;" :: "r"(mbarS), "r"(bytes) : "memory");
}
__device__ __forceinline__ void mbar_wait(unsigned mbarS, unsigned parity) {
    asm volatile(
        "{\n\t.reg .pred P;\n"
        "W_%=:\n\t"
        "mbarrier.try_wait.parity.acquire.cta.shared::cta.b64 P, [%0], %1, 0x989680;\n\t"
        "@P bra D_%=;\n\t"
        "bra W_%=;\n"
        "D_%=:\n\t}"
        :: "r"(mbarS), "r"(parity) : "memory");
}
__device__ __forceinline__ float hclip(float x) {
    return fminf(fmaxf(x, 1e-10f), 1.0f);
}

// ---------------- prep: pack W into per-block swizzled tiles -------------------
// Destination-driven: one thread per packed bf16 element (80*16*4096 = 5.24M).
__global__ void prep_pack(const float* __restrict__ w_str2thal,
                          const float* __restrict__ w_m12m1,
                          const float* __restrict__ w_m12str,
                          const float* __restrict__ w_thal2m1,
                          const float* __restrict__ fixedw) {
    int e = blockIdx.x * blockDim.x + threadIdx.x;
    if (e >= 80 * 16 * 4096) return;

    int bid = e >> 16;              // /65536
    int rem = e & 65535;
    int kt  = rem >> 12;            // 0..15
    int wi  = rem & 4095;
    int row = wi >> 7;              // n-row within 32-row W tile
    int chunk = ((wi >> 3) & 15) ^ (row & 7);
    int kl  = (chunk << 3) | (wi & 7);
    int k   = ((kt & 7) << 7) + kl; // k within 1024-col W block

    float val;
    if (bid < 32) {                 // str: kt<8 -> W00, kt>=8 -> W02
        int n = bid * 32 + row;
        int src = n * Hh + k;
        if (kt < 8) val = -fixedw[src];
        else { float v = hclip(w_m12str[src]); val = (k < NEXC) ? v : 0.0f; }
    } else if (bid < 64) {          // m1: kt<8 -> W21, kt>=8 -> W22
        int n = (bid - 32) * 32 + row;
        int src = n * Hh + k;
        if (kt < 8) val = hclip(w_thal2m1[src]);
        else { float v = hclip(w_m12m1[src]); val = (k < NEXC) ? v : -v; }
    } else {                        // thal: 64n strip; kt<8 rows 0..31, kt>=8 rows 32..63
        int n = (bid - 64) * 64 + ((kt >> 3) << 5) + row;
        int src = n * Hh + k;
        float v = hclip(w_str2thal[src]);
        val = (k < (Hh / 2)) ? v : -v;
    }
    g_Wp[e] = __float2bfloat16(val);
}

// ---------------- init: hn ([b][n]) -> h masters --------------------------------
__global__ void init_kernel(const float* __restrict__ hn) {
    int idx = blockIdx.x * blockDim.x + threadIdx.x;
    if (idx >= Bz * H3) return;
    int b = idx / H3, n = idx - b * H3;
    float v = hn[idx];
    g_hf[0][idx] = v;
    int off = (n >> 7) * 4096 + b * 128 + ((((n >> 3) & 15) ^ (b & 7)) << 3) + (n & 7);
    g_hb[0][off] = __float2bfloat16(v);
}

// ---------------- persistent tensor-core kernel ----------------------------------
__global__ void __launch_bounds__(512, 1) rnn_persist(const float* __restrict__ inp,
                                                      const float* __restrict__ iw,
                                                      float* __restrict__ rnn) {
    extern __shared__ __align__(256) unsigned char smem[];
    // smem: [0,128K) W tiles; [OFF_HA,+40K) ring A; [OFF_HB,+40K) ring B; [OFF_CB,+8K) comb
    __shared__ __align__(8) unsigned long long mbar[17];   // 0..7 ringA, 8..15 ringB, 16 W

    const int tx   = threadIdx.x;
    const int bid  = blockIdx.x;
    const int wid  = tx >> 5;
    const int lane = tx & 31;
    const bool thal = (bid >= 64);

    // ---- block decode ----
    int n0, htA, htB;               // g_hb tile indices for ks0 / ks1 segments
    if (bid < 32)      { n0 = bid * 32;              htA = 0;  htB = 16; }
    else if (bid < 64) { n0 = 2048 + (bid - 32)*32;  htA = 8;  htB = 16; }
    else               { n0 = 1024 + (bid - 64)*64;  htA = 0;  htB = 0;  }

    const unsigned sBase = smem_u32(smem);
    const unsigned mBase = smem_u32(mbar);

    // ---- one-time prologue: barriers + resident W (128KB) ----
    if (tx == 0) {
#pragma unroll
        for (int i = 0; i < 17; i++) mbar_init(mBase + i * 8);
    }
    __syncthreads();
    if (tx == 0) {
        mbar_expect(mBase + 16 * 8, 131072);
        bulk_cp(sBase,         g_Wp + (size_t)bid * 65536,         65536, mBase + 16 * 8);
        bulk_cp(sBase + 65536, g_Wp + (size_t)bid * 65536 + 32768, 65536, mBase + 16 * 8);
    }
    mbar_wait(mBase + 16 * 8, 0);
    __syncthreads();

    // ---- warp roles ----
    const int bt = wid & 1;
    int nh, ks, wtb;
    if (!thal) { ks = wid >> 3; nh = (wid >> 1) & 3; wtb = ks * 8; }
    else       { ks = 0;        nh = wid >> 1;       wtb = (nh >> 2) * 8; }
    const int brow = (thal ? (nh & 3) : nh) * 8 + (lane & 7);
    const unsigned ringOff = (!thal && ks) ? OFF_HB : OFF_HA;
    const int barBase = (!thal && ks) ? 8 : 0;

    // ---- ldmatrix lane addressing ----
    const int am = lane >> 3;
    const int arow = bt * 16 + (am & 1) * 8 + (lane & 7);   // A row (batch)
    const int qa   = am >> 1;
    const int sa   = arow & 7;
    const int grp  = lane >> 3;
    const int sb   = brow & 7;
    const unsigned habase = sBase + ringOff + arow * 256;
    const unsigned wbbase = sBase + brow * 256;

    // ---- epilogue constants ----
    const int g  = lane >> 2, tg = lane & 3;
    const int pn = nh * 8 + 2 * tg;
    const int pb = bt * 16 + g;
    const int ncol = n0 + pn;
    float iwv[2][4];
#pragma unroll
    for (int j = 0; j < 2; j++)
#pragma unroll
        for (int i = 0; i < 4; i++) iwv[j][i] = iw[i * H3 + ncol + j];

    float* sComb = (float*)(smem + OFF_CB);

    unsigned tgt;
    asm volatile("ld.volatile.global.u32 %0, [%1];" : "=r"(tgt) : "l"(&g_gen));

    // =================== time loop ===================
#pragma unroll 1
    for (int t = 0; t < Tz; t++) {
        const int cur = t & 1, nxt = cur ^ 1;
        const unsigned par = (unsigned)(t & 1);
        const __nv_bfloat16* hbc = g_hb[cur];

        // stage first 5 h tiles into each ring
        if (tx == 0) {
#pragma unroll
            for (int i = 0; i < 5; i++) {
                mbar_expect(mBase + i * 8, 8192);
                bulk_cp(sBase + OFF_HA + i * 8192, hbc + (htA + i) * 4096, 8192, mBase + i * 8);
                if (!thal) {
                    mbar_expect(mBase + (8 + i) * 8, 8192);
                    bulk_cp(sBase + OFF_HB + i * 8192, hbc + (htB + i) * 4096, 8192, mBase + (8 + i) * 8);
                }
            }
        }

        float d[2][4];
#pragma unroll
        for (int e = 0; e < 2; e++)
#pragma unroll
            for (int j = 0; j < 4; j++) d[e][j] = 0.f;

#pragma unroll 1
        for (int kt = 0; kt < 8; kt++) {
            mbar_wait(mBase + (barBase + kt) * 8, par);

            const unsigned ha = habase + (kt % 5) * 8192;
            const unsigned wa = wbbase + (wtb + kt) * 8192;
#pragma unroll
            for (int kp = 0; kp < 4; kp++) {
                unsigned b0, b1, b2, b3;
                asm volatile("ldmatrix.sync.aligned.m8n8.x4.shared.b16 {%0,%1,%2,%3}, [%4];"
                             : "=r"(b0), "=r"(b1), "=r"(b2), "=r"(b3)
                             : "r"(wa + (((4 * kp + grp) ^ sb) << 4)));
                unsigned a0, a1, a2, a3;
                asm volatile("ldmatrix.sync.aligned.m8n8.x4.shared.b16 {%0,%1,%2,%3}, [%4];"
                             : "=r"(a0), "=r"(a1), "=r"(a2), "=r"(a3)
                             : "r"(ha + (((4 * kp + qa) ^ sa) << 4)));
                asm volatile("mma.sync.aligned.m16n8k16.row.col.f32.bf16.bf16.f32 "
                             "{%0,%1,%2,%3}, {%4,%5,%6,%7}, {%8,%9}, {%0,%1,%2,%3};"
                             : "+f"(d[0][0]), "+f"(d[0][1]), "+f"(d[0][2]), "+f"(d[0][3])
                             : "r"(a0), "r"(a1), "r"(a2), "r"(a3), "r"(b0), "r"(b1));
                unsigned c0, c1, c2, c3;
                asm volatile("ldmatrix.sync.aligned.m8n8.x4.shared.b16 {%0,%1,%2,%3}, [%4];"
                             : "=r"(c0), "=r"(c1), "=r"(c2), "=r"(c3)
                             : "r"(ha + (((4 * kp + 2 + qa) ^ sa) << 4)));
                asm volatile("mma.sync.aligned.m16n8k16.row.col.f32.bf16.bf16.f32 "
                             "{%0,%1,%2,%3}, {%4,%5,%6,%7}, {%8,%9}, {%0,%1,%2,%3};"
                             : "+f"(d[1][0]), "+f"(d[1][1]), "+f"(d[1][2]), "+f"(d[1][3])
                             : "r"(c0), "r"(c1), "r"(c2), "r"(c3), "r"(b2), "r"(b3));
            }

            // refill slot kt%5 with tile kt+5 once all warps consumed tile kt
            if (kt < 3) {
                __syncthreads();
                if (tx == 0) {
                    int i = kt + 5;
                    mbar_expect(mBase + i * 8, 8192);
                    bulk_cp(sBase + OFF_HA + (i % 5) * 8192, hbc + (htA + i) * 4096, 8192, mBase + i * 8);
                    if (!thal) {
                        mbar_expect(mBase + (8 + i) * 8, 8192);
                        bulk_cp(sBase + OFF_HB + (i % 5) * 8192, hbc + (htB + i) * 4096, 8192, mBase + (8 + i) * 8);
                    }
                }
            }
        }

        float ds[4];
#pragma unroll
        for (int j = 0; j < 4; j++) ds[j] = d[0][j] + d[1][j];

        // ---- in-smem K-split combine (str/m1 only) ----
        bool do_epi = true;
        if (!thal) {
            __syncthreads();                     // all warps done with tiles
            *(float4*)&sComb[tx * 4] = make_float4(ds[0], ds[1], ds[2], ds[3]);
            __syncthreads();
            if (tx < 256) {
                const float4 p = *(const float4*)&sComb[(tx + 256) * 4];
                ds[0] += p.x; ds[1] += p.y; ds[2] += p.z; ds[3] += p.w;
            } else {
                do_epi = false;
            }
        }

        // ---- epilogue: drive + relu; write fp32 master, tiled bf16 operand, rnn ----
        if (do_epi) {
            float* __restrict__ hfn = g_hf[nxt];
            __nv_bfloat16* __restrict__ hbn = g_hb[nxt];
            const float* __restrict__ hfc = g_hf[cur];

#pragma unroll
            for (int half = 0; half < 2; half++) {
                int b = pb + half * 8;
                float4 iv = ((const float4*)inp)[b * Tz + t];
                float v2[2];
#pragma unroll
                for (int j = 0; j < 2; j++) {
                    int n = ncol + j;
                    float drv = iv.x * iwv[j][0] + iv.y * iwv[j][1]
                              + iv.z * iwv[j][2] + iv.w * iwv[j][3];
                    float hp = hfc[b * H3 + n];
                    float v = fmaxf(0.9f * hp + 0.1f * (ds[half * 2 + j] + drv), 0.0f);
                    v2[j] = v;
                    hfn[b * H3 + n] = v;
                    rnn[((size_t)(b * Tz + t)) * H3 + n] = v;
                }
                int n = ncol;
                int off = (n >> 7) * 4096 + b * 128 + ((((n >> 3) & 15) ^ (b & 7)) << 3) + (n & 7);
                __nv_bfloat162 pk;
                pk.x = __float2bfloat16(v2[0]);
                pk.y = __float2bfloat16(v2[1]);
                *(__nv_bfloat162*)&hbn[off] = pk;
            }
        }

        // ---- grid barrier (80 blocks) ----
        __syncthreads();
        if (tx == 0) {
            __threadfence();
            ++tgt;
            if (atomicAdd(&g_cnt, 1u) == NBLK - 1) {
                g_cnt = 0;
                __threadfence();
                atomicExch(&g_gen, tgt);
            } else {
                unsigned curgen;
                do {
                    __nanosleep(64);
                    asm volatile("ld.volatile.global.u32 %0, [%1];" : "=r"(curgen) : "l"(&g_gen));
                } while ((int)(curgen - tgt) < 0);
                __threadfence();
            }
        } else { ++tgt; }
        __syncthreads();
    }
}

// ---------------- heads: mean/std over masked (m1) region ----------------------
__global__ void head_kernel(const float* __restrict__ rnn,
                            const float* __restrict__ mean_w, const float* __restrict__ mean_b,
                            const float* __restrict__ std_w,  const float* __restrict__ std_b,
                            float* __restrict__ mean_out, float* __restrict__ std_out) {
    int warp = blockIdx.x * 8 + (threadIdx.x >> 5);   // = b*512 + t
    int lane = threadIdx.x & 31;
    const float* row = rnn + (size_t)warp * H3 + 2048;
    float sm = 0.0f, ss = 0.0f;
#pragma unroll 8
    for (int i = lane; i < Hh; i += 32) {
        float v = row[i];
        sm += v * mean_w[2048 + i];
        ss += v * std_w[2048 + i];
    }
#pragma unroll
    for (int off = 16; off; off >>= 1) {
        sm += __shfl_down_sync(0xFFFFFFFFu, sm, off);
        ss += __shfl_down_sync(0xFFFFFFFFu, ss, off);
    }
    if (lane == 0) {
        mean_out[warp] = sm + mean_b[0];
        float s = ss + std_b[0];
        std_out[warp] = fminf(fmaxf(s, -5.0f), 10.0f);
    }
}

// ---------------- hn_last copy --------------------------------------------------
__global__ void hn_kernel(const float* __restrict__ rnn, float* __restrict__ hn_out) {
    int idx = blockIdx.x * blockDim.x + threadIdx.x;
    if (idx >= Bz * H3) return;
    int b = idx / H3, n = idx - b * H3;
    hn_out[idx] = rnn[((size_t)(b * Tz + (Tz - 1))) * H3 + n];
}

// ---------------- launch ---------------------------------------------------------
extern "C" void kernel_launch(void* const* d_in, const int* in_sizes, int n_in,
                              void* d_out, int out_size) {
    const float* inp        = (const float*)d_in[0];   // [32,512,4]
    const float* hn         = (const float*)d_in[1];   // [1,32,3072]
    // d_in[2] = w_str2str (unused: its mask is all-zeros in the reference)
    const float* w_str2thal = (const float*)d_in[3];
    const float* w_m12m1    = (const float*)d_in[4];
    const float* w_m12str   = (const float*)d_in[5];
    const float* w_thal2m1  = (const float*)d_in[6];
    const float* fixedw     = (const float*)d_in[7];
    const float* inp_weight = (const float*)d_in[8];   // [4,3072]
    const float* mean_w     = (const float*)d_in[9];   // [1,3072]
    const float* mean_b     = (const float*)d_in[10];  // [1]
    const float* std_w      = (const float*)d_in[11];
    const float* std_b      = (const float*)d_in[12];
    // d_in[13] = sampling flag

    float* out      = (float*)d_out;
    float* mean_out = out;                         // 32*512
    float* std_out  = out + 16384;                 // 32*512
    float* hn_out   = out + 32768;                 // 32*3072
    float* rnn      = out + 131072;                // 32*512*3072

    cudaFuncSetAttribute(rnn_persist, cudaFuncAttributeMaxDynamicSharedMemorySize, SMEM_BYTES);

    prep_pack<<<(80 * 16 * 4096 + 255) / 256, 256>>>(w_str2thal, w_m12m1, w_m12str, w_thal2m1, fixedw);
    init_kernel<<<(Bz * H3 + 255) / 256, 256>>>(hn);

    rnn_persist<<<NBLK, 512, SMEM_BYTES>>>(inp, inp_weight, rnn);

    head_kernel<<<2048, 256>>>(rnn, mean_w, mean_b, std_w, std_b, mean_out, std_out);
    hn_kernel<<<(Bz * H3 + 255) / 256, 256>>>(rnn, hn_out);
}

// round 13
// speedup vs baseline: 1.3866x; 1.1710x over previous
#include <cuda_runtime.h>
#include <cuda_bf16.h>
#include <cstdint>

// ---------------------------------------------------------------------------
// RNN_MultiRegional_SAC — persistent bf16 mma.sync, 80 blocks x 512 threads.
// h = relu(0.9 h + 0.1 (h @ W^T + drive)), 512 steps, B=32, 3H=3072.
// W_rec: 5 nonzero 1024x1024 blocks bf16: [W00=-fixed, W02, W10, W21, W22]
// 80 perfectly-balanced blocks, ONE per SM, W resident in smem (128KB):
//   bid 0..31:  str strip 32n: ks0 warps W00 (h[0:1024]), ks1 warps W02 (h[2048:3072])
//   bid 32..63: m1  strip 32n: ks0 W21 (h[1024:2048]),    ks1 W22 (h[2048:3072])
//   bid 64..79: thal strip 64n: all warps W10 (h[0:1024]), no K-split
// 16 warps/block: (bt = batch half, nh = n-octet, ks = K-half). K-split halves
// combine IN SMEM (aliased into ring A). fp32 master h lives in REGISTERS
// (each thread owns the same 4 outputs every step) — no gmem h master.
// h operand streams via cp.async.bulk into two 6-slot rings (tiles 6,7 refill).
// One grid barrier per step. bf16 mma operands.
// Output (float32): [mean 32*512][std 32*512][hn_last 32*3072][rnn 32*512*3072]
// ---------------------------------------------------------------------------

#define Hh   1024
#define H3   3072
#define Bz   32
#define Tz   512
#define NEXC 717
#define HH   (Hh*Hh)
#define NBLK 80

#define OFF_HA  131072u
#define OFF_HB  180224u
#define SMEM_BYTES 229376   // W 128K + ringA 48K + ringB 48K (comb aliases ringA)

// Packed, per-block-contiguous, pre-swizzled W: [bid 80][kt 16][4096 bf16] = 10.5MB
__device__ __align__(256) __nv_bfloat16 g_Wp[80u * 16u * 4096u];
// bf16 operand h, tiled+swizzled: 24 tiles of 4096; tile tk holds k in
// [tk*128,(tk+1)*128): elem off = b*128 + ((((k>>3)&15)^(b&7))<<3) + (k&7)
__device__ __align__(256) __nv_bfloat16 g_hb[2][24 * 4096];
__device__ unsigned g_cnt;                                   // barrier counter (self-reset)
__device__ unsigned g_gen;                                   // barrier generation

// ---------------- helpers ----------------
__device__ __forceinline__ unsigned smem_u32(const void* p) {
    return (unsigned)__cvta_generic_to_shared(p);
}
__device__ __forceinline__ void bulk_cp(unsigned dstS, const void* srcG, unsigned bytes, unsigned mbarS) {
    asm volatile("cp.async.bulk.shared::cta.global.mbarrier::complete_tx::bytes [%0], [%1], %2, [%3];"
                 :: "r"(dstS), "l"(srcG), "r"(bytes), "r"(mbarS) : "memory");
}
__device__ __forceinline__ void mbar_init(unsigned mbarS) {
    asm volatile("mbarrier.init.shared.b64 [%0], 1;" :: "r"(mbarS) : "memory");
}
__device__ __forceinline__ void mbar_expect(unsigned mbarS, unsigned bytes) {
    asm volatile("mbarrier.arrive.expect_tx.shared.b64 _, [%0], %1;" :: "r"(mbarS), "r"(bytes) : "memory");
}
__device__ __forceinline__ void mbar_wait(unsigned mbarS, unsigned parity) {
    asm volatile(
        "{\n\t.reg .pred P;\n"
        "W_%=:\n\t"
        "mbarrier.try_wait.parity.acquire.cta.shared::cta.b64 P, [%0], %1, 0x989680;\n\t"
        "@P bra D_%=;\n\t"
        "bra W_%=;\n"
        "D_%=:\n\t}"
        :: "r"(mbarS), "r"(parity) : "memory");
}
__device__ __forceinline__ float hclip(float x) {
    return fminf(fmaxf(x, 1e-10f), 1.0f);
}

// ---------------- prep: pack W into per-block swizzled tiles -------------------
__global__ void prep_pack(const float* __restrict__ w_str2thal,
                          const float* __restrict__ w_m12m1,
                          const float* __restrict__ w_m12str,
                          const float* __restrict__ w_thal2m1,
                          const float* __restrict__ fixedw) {
    int e = blockIdx.x * blockDim.x + threadIdx.x;
    if (e >= 80 * 16 * 4096) return;

    int bid = e >> 16;              // /65536
    int rem = e & 65535;
    int kt  = rem >> 12;            // 0..15
    int wi  = rem & 4095;
    int row = wi >> 7;              // n-row within 32-row W tile
    int chunk = ((wi >> 3) & 15) ^ (row & 7);
    int kl  = (chunk << 3) | (wi & 7);
    int k   = ((kt & 7) << 7) + kl; // k within 1024-col W block

    float val;
    if (bid < 32) {                 // str: kt<8 -> W00, kt>=8 -> W02
        int n = bid * 32 + row;
        int src = n * Hh + k;
        if (kt < 8) val = -fixedw[src];
        else { float v = hclip(w_m12str[src]); val = (k < NEXC) ? v : 0.0f; }
    } else if (bid < 64) {          // m1: kt<8 -> W21, kt>=8 -> W22
        int n = (bid - 32) * 32 + row;
        int src = n * Hh + k;
        if (kt < 8) val = hclip(w_thal2m1[src]);
        else { float v = hclip(w_m12m1[src]); val = (k < NEXC) ? v : -v; }
    } else {                        // thal: 64n strip; kt<8 rows 0..31, kt>=8 rows 32..63
        int n = (bid - 64) * 64 + ((kt >> 3) << 5) + row;
        int src = n * Hh + k;
        float v = hclip(w_str2thal[src]);
        val = (k < (Hh / 2)) ? v : -v;
    }
    g_Wp[e] = __float2bfloat16(val);
}

// ---------------- init: hn ([b][n]) -> tiled bf16 operand ----------------------
__global__ void init_kernel(const float* __restrict__ hn) {
    int idx = blockIdx.x * blockDim.x + threadIdx.x;
    if (idx >= Bz * H3) return;
    int b = idx / H3, n = idx - b * H3;
    int off = (n >> 7) * 4096 + b * 128 + ((((n >> 3) & 15) ^ (b & 7)) << 3) + (n & 7);
    g_hb[0][off] = __float2bfloat16(hn[idx]);
}

// ---------------- persistent tensor-core kernel ----------------------------------
__global__ void __launch_bounds__(512, 1) rnn_persist(const float* __restrict__ inp,
                                                      const float* __restrict__ iw,
                                                      const float* __restrict__ hn0,
                                                      float* __restrict__ rnn) {
    extern __shared__ __align__(256) unsigned char smem[];
    // smem: [0,128K) W tiles; [OFF_HA,+48K) ring A (comb aliases); [OFF_HB,+48K) ring B
    __shared__ __align__(8) unsigned long long mbar[17];   // 0..7 ringA, 8..15 ringB, 16 W

    const int tx   = threadIdx.x;
    const int bid  = blockIdx.x;
    const int wid  = tx >> 5;
    const int lane = tx & 31;
    const bool thal = (bid >= 64);

    // ---- block decode ----
    int n0, htA, htB;               // g_hb tile indices for ks0 / ks1 segments
    if (bid < 32)      { n0 = bid * 32;              htA = 0;  htB = 16; }
    else if (bid < 64) { n0 = 2048 + (bid - 32)*32;  htA = 8;  htB = 16; }
    else               { n0 = 1024 + (bid - 64)*64;  htA = 0;  htB = 0;  }

    const unsigned sBase = smem_u32(smem);
    const unsigned mBase = smem_u32(mbar);

    // ---- one-time prologue: barriers + resident W (128KB) ----
    if (tx == 0) {
#pragma unroll
        for (int i = 0; i < 17; i++) mbar_init(mBase + i * 8);
    }
    __syncthreads();
    if (tx == 0) {
        mbar_expect(mBase + 16 * 8, 131072);
        bulk_cp(sBase,         g_Wp + (size_t)bid * 65536,         65536, mBase + 16 * 8);
        bulk_cp(sBase + 65536, g_Wp + (size_t)bid * 65536 + 32768, 65536, mBase + 16 * 8);
    }
    mbar_wait(mBase + 16 * 8, 0);
    __syncthreads();

    // ---- warp roles ----
    const int bt = wid & 1;
    int nh, ks, wtb;
    if (!thal) { ks = wid >> 3; nh = (wid >> 1) & 3; wtb = ks * 8; }
    else       { ks = 0;        nh = wid >> 1;       wtb = (nh >> 2) * 8; }
    const int brow = (thal ? (nh & 3) : nh) * 8 + (lane & 7);
    const unsigned ringOff = (!thal && ks) ? OFF_HB : OFF_HA;
    const int barBase = (!thal && ks) ? 8 : 0;

    // ---- ldmatrix lane addressing ----
    const int am = lane >> 3;
    const int arow = bt * 16 + (am & 1) * 8 + (lane & 7);   // A row (batch)
    const int qa   = am >> 1;
    const int sa   = arow & 7;
    const int grp  = lane >> 3;
    const int sb   = brow & 7;
    const unsigned habase = sBase + ringOff + arow * 256;
    const unsigned wbbase = sBase + brow * 256;

    // ---- epilogue constants ----
    const int g  = lane >> 2, tg = lane & 3;
    const int pn = nh * 8 + 2 * tg;
    const int pb = bt * 16 + g;
    const int ncol = n0 + pn;
    const bool owner = thal || (tx < 256);
    float iwv[2][4];
#pragma unroll
    for (int j = 0; j < 2; j++)
#pragma unroll
        for (int i = 0; i < 4; i++) iwv[j][i] = iw[i * H3 + ncol + j];

    // ---- fp32 master h in registers (owner threads only) ----
    float hm[4];
#pragma unroll
    for (int half = 0; half < 2; half++)
#pragma unroll
        for (int j = 0; j < 2; j++)
            hm[half * 2 + j] = owner ? hn0[(pb + half * 8) * H3 + ncol + j] : 0.0f;

    float* sComb = (float*)(smem + OFF_HA);   // aliases ring A (safe: used post-consume)

    unsigned tgt;
    asm volatile("ld.volatile.global.u32 %0, [%1];" : "=r"(tgt) : "l"(&g_gen));

    // =================== time loop ===================
#pragma unroll 1
    for (int t = 0; t < Tz; t++) {
        const int cur = t & 1, nxt = cur ^ 1;
        const unsigned par = (unsigned)(t & 1);
        const __nv_bfloat16* hbc = g_hb[cur];

        // stage first 6 h tiles into each ring
        if (tx == 0) {
#pragma unroll
            for (int i = 0; i < 6; i++) {
                mbar_expect(mBase + i * 8, 8192);
                bulk_cp(sBase + OFF_HA + i * 8192, hbc + (htA + i) * 4096, 8192, mBase + i * 8);
                if (!thal) {
                    mbar_expect(mBase + (8 + i) * 8, 8192);
                    bulk_cp(sBase + OFF_HB + i * 8192, hbc + (htB + i) * 4096, 8192, mBase + (8 + i) * 8);
                }
            }
        }

        // hoist drive loads (independent of h)
        float4 iva = make_float4(0.f, 0.f, 0.f, 0.f), ivb = iva;
        if (owner) {
            iva = ((const float4*)inp)[pb * Tz + t];
            ivb = ((const float4*)inp)[(pb + 8) * Tz + t];
        }

        float d[2][4];
#pragma unroll
        for (int e = 0; e < 2; e++)
#pragma unroll
            for (int j = 0; j < 4; j++) d[e][j] = 0.f;

#pragma unroll 1
        for (int kt = 0; kt < 8; kt++) {
            mbar_wait(mBase + (barBase + kt) * 8, par);

            const unsigned ha = habase + (kt % 6) * 8192;
            const unsigned wa = wbbase + (wtb + kt) * 8192;
#pragma unroll
            for (int kp = 0; kp < 4; kp++) {
                unsigned b0, b1, b2, b3;
                asm volatile("ldmatrix.sync.aligned.m8n8.x4.shared.b16 {%0,%1,%2,%3}, [%4];"
                             : "=r"(b0), "=r"(b1), "=r"(b2), "=r"(b3)
                             : "r"(wa + (((4 * kp + grp) ^ sb) << 4)));
                unsigned a0, a1, a2, a3;
                asm volatile("ldmatrix.sync.aligned.m8n8.x4.shared.b16 {%0,%1,%2,%3}, [%4];"
                             : "=r"(a0), "=r"(a1), "=r"(a2), "=r"(a3)
                             : "r"(ha + (((4 * kp + qa) ^ sa) << 4)));
                asm volatile("mma.sync.aligned.m16n8k16.row.col.f32.bf16.bf16.f32 "
                             "{%0,%1,%2,%3}, {%4,%5,%6,%7}, {%8,%9}, {%0,%1,%2,%3};"
                             : "+f"(d[0][0]), "+f"(d[0][1]), "+f"(d[0][2]), "+f"(d[0][3])
                             : "r"(a0), "r"(a1), "r"(a2), "r"(a3), "r"(b0), "r"(b1));
                unsigned c0, c1, c2, c3;
                asm volatile("ldmatrix.sync.aligned.m8n8.x4.shared.b16 {%0,%1,%2,%3}, [%4];"
                             : "=r"(c0), "=r"(c1), "=r"(c2), "=r"(c3)
                             : "r"(ha + (((4 * kp + 2 + qa) ^ sa) << 4)));
                asm volatile("mma.sync.aligned.m16n8k16.row.col.f32.bf16.bf16.f32 "
                             "{%0,%1,%2,%3}, {%4,%5,%6,%7}, {%8,%9}, {%0,%1,%2,%3};"
                             : "+f"(d[1][0]), "+f"(d[1][1]), "+f"(d[1][2]), "+f"(d[1][3])
                             : "r"(c0), "r"(c1), "r"(c2), "r"(c3), "r"(b2), "r"(b3));
            }

            // refill slot kt with tile kt+6 (only tiles 6,7 need it)
            if (kt < 2) {
                __syncthreads();
                if (tx == 0) {
                    int i = kt + 6;
                    mbar_expect(mBase + i * 8, 8192);
                    bulk_cp(sBase + OFF_HA + (i % 6) * 8192, hbc + (htA + i) * 4096, 8192, mBase + i * 8);
                    if (!thal) {
                        mbar_expect(mBase + (8 + i) * 8, 8192);
                        bulk_cp(sBase + OFF_HB + (i % 6) * 8192, hbc + (htB + i) * 4096, 8192, mBase + (8 + i) * 8);
                    }
                }
            }
        }

        float ds[4];
#pragma unroll
        for (int j = 0; j < 4; j++) ds[j] = d[0][j] + d[1][j];

        // ---- in-smem K-split combine (str/m1 only) ----
        if (!thal) {
            __syncthreads();                     // all warps done with ring tiles
            *(float4*)&sComb[tx * 4] = make_float4(ds[0], ds[1], ds[2], ds[3]);
            __syncthreads();
            if (tx < 256) {
                const float4 p = *(const float4*)&sComb[(tx + 256) * 4];
                ds[0] += p.x; ds[1] += p.y; ds[2] += p.z; ds[3] += p.w;
            }
        }

        // ---- epilogue: drive + relu; reg master update; write bf16 operand + rnn ----
        if (owner) {
            __nv_bfloat16* __restrict__ hbn = g_hb[nxt];
#pragma unroll
            for (int half = 0; half < 2; half++) {
                int b = pb + half * 8;
                float4 iv = half ? ivb : iva;
                float v2[2];
#pragma unroll
                for (int j = 0; j < 2; j++) {
                    int n = ncol + j;
                    float drv = iv.x * iwv[j][0] + iv.y * iwv[j][1]
                              + iv.z * iwv[j][2] + iv.w * iwv[j][3];
                    float v = fmaxf(0.9f * hm[half * 2 + j] + 0.1f * (ds[half * 2 + j] + drv), 0.0f);
                    hm[half * 2 + j] = v;
                    v2[j] = v;
                    rnn[((size_t)(b * Tz + t)) * H3 + n] = v;
                }
                int n = ncol;
                int off = (n >> 7) * 4096 + b * 128 + ((((n >> 3) & 15) ^ (b & 7)) << 3) + (n & 7);
                __nv_bfloat162 pk;
                pk.x = __float2bfloat16(v2[0]);
                pk.y = __float2bfloat16(v2[1]);
                *(__nv_bfloat162*)&hbn[off] = pk;
            }
        }

        // ---- grid barrier (80 blocks) ----
        __syncthreads();
        if (tx == 0) {
            __threadfence();
            ++tgt;
            if (atomicAdd(&g_cnt, 1u) == NBLK - 1) {
                g_cnt = 0;
                __threadfence();
                atomicExch(&g_gen, tgt);
            } else {
                unsigned curgen;
                do {
                    __nanosleep(32);
                    asm volatile("ld.volatile.global.u32 %0, [%1];" : "=r"(curgen) : "l"(&g_gen));
                } while ((int)(curgen - tgt) < 0);
                __threadfence();
            }
        } else { ++tgt; }
        __syncthreads();
    }
}

// ---------------- heads: mean/std over masked (m1) region ----------------------
__global__ void head_kernel(const float* __restrict__ rnn,
                            const float* __restrict__ mean_w, const float* __restrict__ mean_b,
                            const float* __restrict__ std_w,  const float* __restrict__ std_b,
                            float* __restrict__ mean_out, float* __restrict__ std_out) {
    int warp = blockIdx.x * 8 + (threadIdx.x >> 5);   // = b*512 + t
    int lane = threadIdx.x & 31;
    const float* row = rnn + (size_t)warp * H3 + 2048;
    float sm = 0.0f, ss = 0.0f;
#pragma unroll 8
    for (int i = lane; i < Hh; i += 32) {
        float v = row[i];
        sm += v * mean_w[2048 + i];
        ss += v * std_w[2048 + i];
    }
#pragma unroll
    for (int off = 16; off; off >>= 1) {
        sm += __shfl_down_sync(0xFFFFFFFFu, sm, off);
        ss += __shfl_down_sync(0xFFFFFFFFu, ss, off);
    }
    if (lane == 0) {
        mean_out[warp] = sm + mean_b[0];
        float s = ss + std_b[0];
        std_out[warp] = fminf(fmaxf(s, -5.0f), 10.0f);
    }
}

// ---------------- hn_last copy --------------------------------------------------
__global__ void hn_kernel(const float* __restrict__ rnn, float* __restrict__ hn_out) {
    int idx = blockIdx.x * blockDim.x + threadIdx.x;
    if (idx >= Bz * H3) return;
    int b = idx / H3, n = idx - b * H3;
    hn_out[idx] = rnn[((size_t)(b * Tz + (Tz - 1))) * H3 + n];
}

// ---------------- launch ---------------------------------------------------------
extern "C" void kernel_launch(void* const* d_in, const int* in_sizes, int n_in,
                              void* d_out, int out_size) {
    const float* inp        = (const float*)d_in[0];   // [32,512,4]
    const float* hn         = (const float*)d_in[1];   // [1,32,3072]
    // d_in[2] = w_str2str (unused: its mask is all-zeros in the reference)
    const float* w_str2thal = (const float*)d_in[3];
    const float* w_m12m1    = (const float*)d_in[4];
    const float* w_m12str   = (const float*)d_in[5];
    const float* w_thal2m1  = (const float*)d_in[6];
    const float* fixedw     = (const float*)d_in[7];
    const float* inp_weight = (const float*)d_in[8];   // [4,3072]
    const float* mean_w     = (const float*)d_in[9];   // [1,3072]
    const float* mean_b     = (const float*)d_in[10];  // [1]
    const float* std_w      = (const float*)d_in[11];
    const float* std_b      = (const float*)d_in[12];
    // d_in[13] = sampling flag

    float* out      = (float*)d_out;
    float* mean_out = out;                         // 32*512
    float* std_out  = out + 16384;                 // 32*512
    float* hn_out   = out + 32768;                 // 32*3072
    float* rnn      = out + 131072;                // 32*512*3072

    cudaFuncSetAttribute(rnn_persist, cudaFuncAttributeMaxDynamicSharedMemorySize, SMEM_BYTES);

    prep_pack<<<(80 * 16 * 4096 + 255) / 256, 256>>>(w_str2thal, w_m12m1, w_m12str, w_thal2m1, fixedw);
    init_kernel<<<(Bz * H3 + 255) / 256, 256>>>(hn);

    rnn_persist<<<NBLK, 512, SMEM_BYTES>>>(inp, inp_weight, hn, rnn);

    head_kernel<<<2048, 256>>>(rnn, mean_w, mean_b, std_w, std_b, mean_out, std_out);
    hn_kernel<<<(Bz * H3 + 255) / 256, 256>>>(rnn, hn_out);
}

// round 14
// speedup vs baseline: 1.5076x; 1.0873x over previous
#include <cuda_runtime.h>
#include <cuda_bf16.h>
#include <cstdint>

// ---------------------------------------------------------------------------
// RNN_MultiRegional_SAC — persistent bf16 mma.sync, per-tile dataflow flags.
// h = relu(0.9 h + 0.1 (h @ W^T + drive)), 512 steps, B=32, 3H=3072.
// W_rec: 5 nonzero 1024x1024 blocks bf16: [W00=-fixed, W02, W10, W21, W22]
// 80 blocks, ONE per SM, W resident in smem (128KB):
//   bid 0..31:  str strip 32n: ks0 W00 (h tiles 0..7),  ks1 W02 (h tiles 16..23)
//   bid 32..63: m1  strip 32n: ks0 W21 (h tiles 8..15), ks1 W22 (h tiles 16..23)
//   bid 64..79: thal strip 64n: all warps W10 (h tiles 0..7)
// NO grid barrier: producers arrive on per-(t,tile) flags (24 distinct addrs,
// 2-4 arrivals each); consumers poll only the tiles they need. h operand ring
// g_hb is DEPTH 4 — the flag dependency chain bounds cross-block skew to <3
// steps, so no consumer can still read a buffer being overwritten.
// fp32 master h in registers. K-split combine in smem (aliases ring A).
// Output (float32): [mean 32*512][std 32*512][hn_last 32*3072][rnn 32*512*3072]
// ---------------------------------------------------------------------------

#define Hh   1024
#define H3   3072
#define Bz   32
#define Tz   512
#define NEXC 717
#define HH   (Hh*Hh)
#define NBLK 80

#define OFF_HA  131072u
#define OFF_HB  180224u
#define SMEM_BYTES 229376   // W 128K + ringA 48K + ringB 48K (comb aliases ringA)

// Packed, per-block-contiguous, pre-swizzled W: [bid 80][kt 16][4096 bf16] = 10.5MB
__device__ __align__(256) __nv_bfloat16 g_Wp[80u * 16u * 4096u];
// bf16 operand h, tiled+swizzled, DEPTH-4 ring: 24 tiles of 4096; tile tk holds
// k in [tk*128,(tk+1)*128): elem off = b*128 + ((((k>>3)&15)^(b&7))<<3) + (k&7)
__device__ __align__(256) __nv_bfloat16 g_hb[4][24 * 4096];
__device__ int g_tflag[Tz * 24];    // per-(step,tile) producer arrivals

// ---------------- helpers ----------------
__device__ __forceinline__ unsigned smem_u32(const void* p) {
    return (unsigned)__cvta_generic_to_shared(p);
}
__device__ __forceinline__ void bulk_cp(unsigned dstS, const void* srcG, unsigned bytes, unsigned mbarS) {
    asm volatile("cp.async.bulk.shared::cta.global.mbarrier::complete_tx::bytes [%0], [%1], %2, [%3];"
                 :: "r"(dstS), "l"(srcG), "r"(bytes), "r"(mbarS) : "memory");
}
__device__ __forceinline__ void mbar_init(unsigned mbarS) {
    asm volatile("mbarrier.init.shared.b64 [%0], 1;" :: "r"(mbarS) : "memory");
}
__device__ __forceinline__ void mbar_expect(unsigned mbarS, unsigned bytes) {
    asm volatile("mbarrier.arrive.expect_tx.shared.b64 _, [%0], %1;" :: "r"(mbarS), "r"(bytes) : "memory");
}
__device__ __forceinline__ void mbar_wait(unsigned mbarS, unsigned parity) {
    asm volatile(
        "{\n\t.reg .pred P;\n"
        "W_%=:\n\t"
        "mbarrier.try_wait.parity.acquire.cta.shared::cta.b64 P, [%0], %1, 0x989680;\n\t"
        "@P bra D_%=;\n\t"
        "bra W_%=;\n"
        "D_%=:\n\t}"
        :: "r"(mbarS), "r"(parity) : "memory");
}
__device__ __forceinline__ void poll_flag(const int* p, int expect) {
    int v;
    do {
        asm volatile("ld.acquire.gpu.global.b32 %0, [%1];" : "=r"(v) : "l"(p));
    } while (v < expect);
}
__device__ __forceinline__ int texpect(int tile) {
    return (tile < 8) ? 4 : ((tile < 16) ? 2 : 4);
}
__device__ __forceinline__ float hclip(float x) {
    return fminf(fmaxf(x, 1e-10f), 1.0f);
}

// ---------------- prep: pack W into per-block swizzled tiles + zero flags ------
__global__ void prep_pack(const float* __restrict__ w_str2thal,
                          const float* __restrict__ w_m12m1,
                          const float* __restrict__ w_m12str,
                          const float* __restrict__ w_thal2m1,
                          const float* __restrict__ fixedw) {
    int e = blockIdx.x * blockDim.x + threadIdx.x;
    if (e >= 80 * 16 * 4096) return;
    if (e < Tz * 24) g_tflag[e] = 0;

    int bid = e >> 16;              // /65536
    int rem = e & 65535;
    int kt  = rem >> 12;            // 0..15
    int wi  = rem & 4095;
    int row = wi >> 7;              // n-row within 32-row W tile
    int chunk = ((wi >> 3) & 15) ^ (row & 7);
    int kl  = (chunk << 3) | (wi & 7);
    int k   = ((kt & 7) << 7) + kl; // k within 1024-col W block

    float val;
    if (bid < 32) {                 // str: kt<8 -> W00, kt>=8 -> W02
        int n = bid * 32 + row;
        int src = n * Hh + k;
        if (kt < 8) val = -fixedw[src];
        else { float v = hclip(w_m12str[src]); val = (k < NEXC) ? v : 0.0f; }
    } else if (bid < 64) {          // m1: kt<8 -> W21, kt>=8 -> W22
        int n = (bid - 32) * 32 + row;
        int src = n * Hh + k;
        if (kt < 8) val = hclip(w_thal2m1[src]);
        else { float v = hclip(w_m12m1[src]); val = (k < NEXC) ? v : -v; }
    } else {                        // thal: 64n strip; kt<8 rows 0..31, kt>=8 rows 32..63
        int n = (bid - 64) * 64 + ((kt >> 3) << 5) + row;
        int src = n * Hh + k;
        float v = hclip(w_str2thal[src]);
        val = (k < (Hh / 2)) ? v : -v;
    }
    g_Wp[e] = __float2bfloat16(val);
}

// ---------------- init: hn ([b][n]) -> tiled bf16 operand (ring slot 0) --------
__global__ void init_kernel(const float* __restrict__ hn) {
    int idx = blockIdx.x * blockDim.x + threadIdx.x;
    if (idx >= Bz * H3) return;
    int b = idx / H3, n = idx - b * H3;
    int off = (n >> 7) * 4096 + b * 128 + ((((n >> 3) & 15) ^ (b & 7)) << 3) + (n & 7);
    g_hb[0][off] = __float2bfloat16(hn[idx]);
}

// ---------------- persistent tensor-core kernel ----------------------------------
__global__ void __launch_bounds__(512, 1) rnn_persist(const float* __restrict__ inp,
                                                      const float* __restrict__ iw,
                                                      const float* __restrict__ hn0,
                                                      float* __restrict__ rnn) {
    extern __shared__ __align__(256) unsigned char smem[];
    // smem: [0,128K) W tiles; [OFF_HA,+48K) ring A (comb aliases); [OFF_HB,+48K) ring B
    __shared__ __align__(8) unsigned long long mbar[17];   // 0..7 ringA, 8..15 ringB, 16 W

    const int tx   = threadIdx.x;
    const int bid  = blockIdx.x;
    const int wid  = tx >> 5;
    const int lane = tx & 31;
    const bool thal = (bid >= 64);

    // ---- block decode ----
    int n0, htA, htB, myTile;       // g_hb tile indices (tile = 4096-elem unit)
    if (bid < 32)      { n0 = bid * 32;              htA = 0;  htB = 16; myTile = bid >> 2; }
    else if (bid < 64) { n0 = 2048 + (bid - 32)*32;  htA = 8;  htB = 16; myTile = 16 + ((bid - 32) >> 2); }
    else               { n0 = 1024 + (bid - 64)*64;  htA = 0;  htB = 0;  myTile = 8 + ((bid - 64) >> 1); }

    const unsigned sBase = smem_u32(smem);
    const unsigned mBase = smem_u32(mbar);

    // ---- one-time prologue: barriers + resident W (128KB) ----
    if (tx == 0) {
#pragma unroll
        for (int i = 0; i < 17; i++) mbar_init(mBase + i * 8);
    }
    __syncthreads();
    if (tx == 0) {
        mbar_expect(mBase + 16 * 8, 131072);
        bulk_cp(sBase,         g_Wp + (size_t)bid * 65536,         65536, mBase + 16 * 8);
        bulk_cp(sBase + 65536, g_Wp + (size_t)bid * 65536 + 32768, 65536, mBase + 16 * 8);
    }
    mbar_wait(mBase + 16 * 8, 0);
    __syncthreads();

    // ---- warp roles ----
    const int bt = wid & 1;
    int nh, ks, wtb;
    if (!thal) { ks = wid >> 3; nh = (wid >> 1) & 3; wtb = ks * 8; }
    else       { ks = 0;        nh = wid >> 1;       wtb = (nh >> 2) * 8; }
    const int brow = (thal ? (nh & 3) : nh) * 8 + (lane & 7);
    const unsigned ringOff = (!thal && ks) ? OFF_HB : OFF_HA;
    const int barBase = (!thal && ks) ? 8 : 0;

    // ---- ldmatrix lane addressing ----
    const int am = lane >> 3;
    const int arow = bt * 16 + (am & 1) * 8 + (lane & 7);   // A row (batch)
    const int qa   = am >> 1;
    const int sa   = arow & 7;
    const int grp  = lane >> 3;
    const int sb   = brow & 7;
    const unsigned habase = sBase + ringOff + arow * 256;
    const unsigned wbbase = sBase + brow * 256;

    // ---- epilogue constants ----
    const int g  = lane >> 2, tg = lane & 3;
    const int pn = nh * 8 + 2 * tg;
    const int pb = bt * 16 + g;
    const int ncol = n0 + pn;
    const bool owner = thal || (tx < 256);
    float iwv[2][4];
#pragma unroll
    for (int j = 0; j < 2; j++)
#pragma unroll
        for (int i = 0; i < 4; i++) iwv[j][i] = iw[i * H3 + ncol + j];

    // ---- fp32 master h in registers (owner threads only) ----
    float hm[4];
#pragma unroll
    for (int half = 0; half < 2; half++)
#pragma unroll
        for (int j = 0; j < 2; j++)
            hm[half * 2 + j] = owner ? hn0[(pb + half * 8) * H3 + ncol + j] : 0.0f;

    float* sComb = (float*)(smem + OFF_HA);   // aliases ring A (safe: used post-consume)

    // =================== time loop ===================
#pragma unroll 1
    for (int t = 0; t < Tz; t++) {
        const unsigned par = (unsigned)(t & 1);
        const __nv_bfloat16* hbc = g_hb[t & 3];
        __nv_bfloat16* hbn = g_hb[(t + 1) & 3];

        // ---- staging: warps 0..5 ring A tiles 0..5; warps 6..11 ring B ----
        if (lane == 0) {
            if (wid < 6) {
                int tile = htA + wid;
                if (t > 0) poll_flag(&g_tflag[(t - 1) * 24 + tile], texpect(tile));
                mbar_expect(mBase + wid * 8, 8192);
                bulk_cp(sBase + OFF_HA + wid * 8192, hbc + tile * 4096, 8192, mBase + wid * 8);
            } else if (wid < 12 && !thal) {
                int i = wid - 6;
                int tile = htB + i;
                if (t > 0) poll_flag(&g_tflag[(t - 1) * 24 + tile], texpect(tile));
                mbar_expect(mBase + (8 + i) * 8, 8192);
                bulk_cp(sBase + OFF_HB + i * 8192, hbc + tile * 4096, 8192, mBase + (8 + i) * 8);
            }
        }

        // hoist drive loads (independent of h)
        float4 iva = make_float4(0.f, 0.f, 0.f, 0.f), ivb = iva;
        if (owner) {
            iva = ((const float4*)inp)[pb * Tz + t];
            ivb = ((const float4*)inp)[(pb + 8) * Tz + t];
        }

        float d[2][4];
#pragma unroll
        for (int e = 0; e < 2; e++)
#pragma unroll
            for (int j = 0; j < 4; j++) d[e][j] = 0.f;

#pragma unroll 1
        for (int kt = 0; kt < 8; kt++) {
            mbar_wait(mBase + (barBase + kt) * 8, par);

            const unsigned ha = habase + (kt % 6) * 8192;
            const unsigned wa = wbbase + (wtb + kt) * 8192;
#pragma unroll
            for (int kp = 0; kp < 4; kp++) {
                unsigned b0, b1, b2, b3;
                asm volatile("ldmatrix.sync.aligned.m8n8.x4.shared.b16 {%0,%1,%2,%3}, [%4];"
                             : "=r"(b0), "=r"(b1), "=r"(b2), "=r"(b3)
                             : "r"(wa + (((4 * kp + grp) ^ sb) << 4)));
                unsigned a0, a1, a2, a3;
                asm volatile("ldmatrix.sync.aligned.m8n8.x4.shared.b16 {%0,%1,%2,%3}, [%4];"
                             : "=r"(a0), "=r"(a1), "=r"(a2), "=r"(a3)
                             : "r"(ha + (((4 * kp + qa) ^ sa) << 4)));
                asm volatile("mma.sync.aligned.m16n8k16.row.col.f32.bf16.bf16.f32 "
                             "{%0,%1,%2,%3}, {%4,%5,%6,%7}, {%8,%9}, {%0,%1,%2,%3};"
                             : "+f"(d[0][0]), "+f"(d[0][1]), "+f"(d[0][2]), "+f"(d[0][3])
                             : "r"(a0), "r"(a1), "r"(a2), "r"(a3), "r"(b0), "r"(b1));
                unsigned c0, c1, c2, c3;
                asm volatile("ldmatrix.sync.aligned.m8n8.x4.shared.b16 {%0,%1,%2,%3}, [%4];"
                             : "=r"(c0), "=r"(c1), "=r"(c2), "=r"(c3)
                             : "r"(ha + (((4 * kp + 2 + qa) ^ sa) << 4)));
                asm volatile("mma.sync.aligned.m16n8k16.row.col.f32.bf16.bf16.f32 "
                             "{%0,%1,%2,%3}, {%4,%5,%6,%7}, {%8,%9}, {%0,%1,%2,%3};"
                             : "+f"(d[1][0]), "+f"(d[1][1]), "+f"(d[1][2]), "+f"(d[1][3])
                             : "r"(c0), "r"(c1), "r"(c2), "r"(c3), "r"(b2), "r"(b3));
            }

            // refill slot kt with tile kt+6 (only tiles 6,7; flags almost surely set)
            if (kt < 2) {
                __syncthreads();
                if (tx == 0) {
                    int i = kt + 6;
                    int tileA = htA + i;
                    if (t > 0) poll_flag(&g_tflag[(t - 1) * 24 + tileA], texpect(tileA));
                    mbar_expect(mBase + i * 8, 8192);
                    bulk_cp(sBase + OFF_HA + (i % 6) * 8192, hbc + tileA * 4096, 8192, mBase + i * 8);
                    if (!thal) {
                        int tileB = htB + i;
                        if (t > 0) poll_flag(&g_tflag[(t - 1) * 24 + tileB], texpect(tileB));
                        mbar_expect(mBase + (8 + i) * 8, 8192);
                        bulk_cp(sBase + OFF_HB + (i % 6) * 8192, hbc + tileB * 4096, 8192, mBase + (8 + i) * 8);
                    }
                }
            }
        }

        float ds[4];
#pragma unroll
        for (int j = 0; j < 4; j++) ds[j] = d[0][j] + d[1][j];

        // ---- in-smem K-split combine (str/m1 only) ----
        if (!thal) {
            __syncthreads();                     // all warps done with ring tiles
            *(float4*)&sComb[tx * 4] = make_float4(ds[0], ds[1], ds[2], ds[3]);
            __syncthreads();
            if (tx < 256) {
                const float4 p = *(const float4*)&sComb[(tx + 256) * 4];
                ds[0] += p.x; ds[1] += p.y; ds[2] += p.z; ds[3] += p.w;
            }
        }

        // ---- epilogue: relu update in registers; write bf16 operand (dependency) ----
        if (owner) {
#pragma unroll
            for (int half = 0; half < 2; half++) {
                float4 iv = half ? ivb : iva;
                float v2[2];
#pragma unroll
                for (int j = 0; j < 2; j++) {
                    float drv = iv.x * iwv[j][0] + iv.y * iwv[j][1]
                              + iv.z * iwv[j][2] + iv.w * iwv[j][3];
                    float v = fmaxf(0.9f * hm[half * 2 + j] + 0.1f * (ds[half * 2 + j] + drv), 0.0f);
                    hm[half * 2 + j] = v;
                    v2[j] = v;
                }
                int b = pb + half * 8;
                int n = ncol;
                int off = (n >> 7) * 4096 + b * 128 + ((((n >> 3) & 15) ^ (b & 7)) << 3) + (n & 7);
                __nv_bfloat162 pk;
                pk.x = __float2bfloat16(v2[0]);
                pk.y = __float2bfloat16(v2[1]);
                *(__nv_bfloat162*)&hbn[off] = pk;
            }
        }

        // ---- producer arrival on per-tile flag, then deferred rnn stores ----
        __syncthreads();
        if (tx == 0) {
            __threadfence();
            atomicAdd(&g_tflag[t * 24 + myTile], 1);
        }
        if (owner) {
#pragma unroll
            for (int half = 0; half < 2; half++) {
                int b = pb + half * 8;
#pragma unroll
                for (int j = 0; j < 2; j++)
                    rnn[((size_t)(b * Tz + t)) * H3 + ncol + j] = hm[half * 2 + j];
            }
        }
    }
}

// ---------------- heads: mean/std over masked (m1) region ----------------------
__global__ void head_kernel(const float* __restrict__ rnn,
                            const float* __restrict__ mean_w, const float* __restrict__ mean_b,
                            const float* __restrict__ std_w,  const float* __restrict__ std_b,
                            float* __restrict__ mean_out, float* __restrict__ std_out) {
    int warp = blockIdx.x * 8 + (threadIdx.x >> 5);   // = b*512 + t
    int lane = threadIdx.x & 31;
    const float* row = rnn + (size_t)warp * H3 + 2048;
    float sm = 0.0f, ss = 0.0f;
#pragma unroll 8
    for (int i = lane; i < Hh; i += 32) {
        float v = row[i];
        sm += v * mean_w[2048 + i];
        ss += v * std_w[2048 + i];
    }
#pragma unroll
    for (int off = 16; off; off >>= 1) {
        sm += __shfl_down_sync(0xFFFFFFFFu, sm, off);
        ss += __shfl_down_sync(0xFFFFFFFFu, ss, off);
    }
    if (lane == 0) {
        mean_out[warp] = sm + mean_b[0];
        float s = ss + std_b[0];
        std_out[warp] = fminf(fmaxf(s, -5.0f), 10.0f);
    }
}

// ---------------- hn_last copy --------------------------------------------------
__global__ void hn_kernel(const float* __restrict__ rnn, float* __restrict__ hn_out) {
    int idx = blockIdx.x * blockDim.x + threadIdx.x;
    if (idx >= Bz * H3) return;
    int b = idx / H3, n = idx - b * H3;
    hn_out[idx] = rnn[((size_t)(b * Tz + (Tz - 1))) * H3 + n];
}

// ---------------- launch ---------------------------------------------------------
extern "C" void kernel_launch(void* const* d_in, const int* in_sizes, int n_in,
                              void* d_out, int out_size) {
    const float* inp        = (const float*)d_in[0];   // [32,512,4]
    const float* hn         = (const float*)d_in[1];   // [1,32,3072]
    // d_in[2] = w_str2str (unused: its mask is all-zeros in the reference)
    const float* w_str2thal = (const float*)d_in[3];
    const float* w_m12m1    = (const float*)d_in[4];
    const float* w_m12str   = (const float*)d_in[5];
    const float* w_thal2m1  = (const float*)d_in[6];
    const float* fixedw     = (const float*)d_in[7];
    const float* inp_weight = (const float*)d_in[8];   // [4,3072]
    const float* mean_w     = (const float*)d_in[9];   // [1,3072]
    const float* mean_b     = (const float*)d_in[10];  // [1]
    const float* std_w      = (const float*)d_in[11];
    const float* std_b      = (const float*)d_in[12];
    // d_in[13] = sampling flag

    float* out      = (float*)d_out;
    float* mean_out = out;                         // 32*512
    float* std_out  = out + 16384;                 // 32*512
    float* hn_out   = out + 32768;                 // 32*3072
    float* rnn      = out + 131072;                // 32*512*3072

    cudaFuncSetAttribute(rnn_persist, cudaFuncAttributeMaxDynamicSharedMemorySize, SMEM_BYTES);

    prep_pack<<<(80 * 16 * 4096 + 255) / 256, 256>>>(w_str2thal, w_m12m1, w_m12str, w_thal2m1, fixedw);
    init_kernel<<<(Bz * H3 + 255) / 256, 256>>>(hn);

    rnn_persist<<<NBLK, 512, SMEM_BYTES>>>(inp, inp_weight, hn, rnn);

    head_kernel<<<2048, 256>>>(rnn, mean_w, mean_b, std_w, std_b, mean_out, std_out);
    hn_kernel<<<(Bz * H3 + 255) / 256, 256>>>(rnn, hn_out);
}

// round 15
// speedup vs baseline: 1.5880x; 1.0534x over previous
#include <cuda_runtime.h>
#include <cuda_bf16.h>
#include <cstdint>

// ---------------------------------------------------------------------------
// RNN_MultiRegional_SAC — persistent bf16 mma.sync, per-tile dataflow flags,
// decoupled K-split warp groups.
// h = relu(0.9 h + 0.1 (h @ W^T + drive)), 512 steps, B=32, 3H=3072.
// 80 blocks, ONE per SM, W resident in smem (128KB):
//   bid 0..31:  str strip 32n: grpA W00 (h tiles 0..7),  grpB W02 (h tiles 16..23)
//   bid 32..63: m1  strip 32n: grpA W21 (h tiles 8..15), grpB W22 (h tiles 16..23)
//   bid 64..79: thal strip 64n: all warps W10 (h tiles 0..7)
// Non-thal: group A (warps 0..7) consumes ring A + does epilogue/flag; group B
// (warps 8..15) consumes ring B, writes partials to parity-buffered sComb,
// crosses ONE parity-alternating combine barrier (ids 3/4) and immediately
// stages ring B for step t+1 (overlaps A's epilogue). Group-scoped refill
// barriers (ids 1/2). Flags: per-(t,tile), 24 distinct addrs; depth-4 g_hb ring.
// fp32 master h in registers; rnn stores deferred one step.
// Output (float32): [mean 32*512][std 32*512][hn_last 32*3072][rnn 32*512*3072]
// ---------------------------------------------------------------------------

#define Hh   1024
#define H3   3072
#define Bz   32
#define Tz   512
#define NEXC 717
#define HH   (Hh*Hh)
#define NBLK 80

#define OFF_HA  131072u              // ring A: 6 x 8KB
#define OFF_HB  180224u              // ring B: 5 x 8KB
#define OFF_CB  221184u              // combine: 2 x 4KB (parity)
#define SMEM_BYTES 229376

// Packed, per-block-contiguous, pre-swizzled W: [bid 80][kt 16][4096 bf16] = 10.5MB
__device__ __align__(256) __nv_bfloat16 g_Wp[80u * 16u * 4096u];
// bf16 operand h, tiled+swizzled, DEPTH-4 ring: 24 tiles of 4096; tile tk holds
// k in [tk*128,(tk+1)*128): elem off = b*128 + ((((k>>3)&15)^(b&7))<<3) + (k&7)
__device__ __align__(256) __nv_bfloat16 g_hb[4][24 * 4096];
__device__ int g_tflag[Tz * 24];    // per-(step,tile) producer arrivals

// ---------------- helpers ----------------
__device__ __forceinline__ unsigned smem_u32(const void* p) {
    return (unsigned)__cvta_generic_to_shared(p);
}
__device__ __forceinline__ void bulk_cp(unsigned dstS, const void* srcG, unsigned bytes, unsigned mbarS) {
    asm volatile("cp.async.bulk.shared::cta.global.mbarrier::complete_tx::bytes [%0], [%1], %2, [%3];"
                 :: "r"(dstS), "l"(srcG), "r"(bytes), "r"(mbarS) : "memory");
}
__device__ __forceinline__ void mbar_init(unsigned mbarS) {
    asm volatile("mbarrier.init.shared.b64 [%0], 1;" :: "r"(mbarS) : "memory");
}
__device__ __forceinline__ void mbar_expect(unsigned mbarS, unsigned bytes) {
    asm volatile("mbarrier.arrive.expect_tx.shared.b64 _, [%0], %1;" :: "r"(mbarS), "r"(bytes) : "memory");
}
__device__ __forceinline__ void mbar_wait(unsigned mbarS, unsigned parity) {
    asm volatile(
        "{\n\t.reg .pred P;\n"
        "W_%=:\n\t"
        "mbarrier.try_wait.parity.acquire.cta.shared::cta.b64 P, [%0], %1, 0x989680;\n\t"
        "@P bra D_%=;\n\t"
        "bra W_%=;\n"
        "D_%=:\n\t}"
        :: "r"(mbarS), "r"(parity) : "memory");
}
__device__ __forceinline__ void poll_flag(const int* p, int expect) {
    int v;
    do {
        asm volatile("ld.acquire.gpu.global.b32 %0, [%1];" : "=r"(v) : "l"(p));
    } while (v < expect);
}
__device__ __forceinline__ int texpect(int tile) {
    return (tile < 8) ? 4 : ((tile < 16) ? 2 : 4);
}
__device__ __forceinline__ float hclip(float x) {
    return fminf(fmaxf(x, 1e-10f), 1.0f);
}
#define BARS(id, cnt) asm volatile("bar.sync " #id ", " #cnt ";" ::: "memory")

// ---------------- prep: pack W into per-block swizzled tiles + zero flags ------
__global__ void prep_pack(const float* __restrict__ w_str2thal,
                          const float* __restrict__ w_m12m1,
                          const float* __restrict__ w_m12str,
                          const float* __restrict__ w_thal2m1,
                          const float* __restrict__ fixedw) {
    int e = blockIdx.x * blockDim.x + threadIdx.x;
    if (e >= 80 * 16 * 4096) return;
    if (e < Tz * 24) g_tflag[e] = 0;

    int bid = e >> 16;              // /65536
    int rem = e & 65535;
    int kt  = rem >> 12;            // 0..15
    int wi  = rem & 4095;
    int row = wi >> 7;              // n-row within 32-row W tile
    int chunk = ((wi >> 3) & 15) ^ (row & 7);
    int kl  = (chunk << 3) | (wi & 7);
    int k   = ((kt & 7) << 7) + kl; // k within 1024-col W block

    float val;
    if (bid < 32) {                 // str: kt<8 -> W00, kt>=8 -> W02
        int n = bid * 32 + row;
        int src = n * Hh + k;
        if (kt < 8) val = -fixedw[src];
        else { float v = hclip(w_m12str[src]); val = (k < NEXC) ? v : 0.0f; }
    } else if (bid < 64) {          // m1: kt<8 -> W21, kt>=8 -> W22
        int n = (bid - 32) * 32 + row;
        int src = n * Hh + k;
        if (kt < 8) val = hclip(w_thal2m1[src]);
        else { float v = hclip(w_m12m1[src]); val = (k < NEXC) ? v : -v; }
    } else {                        // thal: 64n strip; kt<8 rows 0..31, kt>=8 rows 32..63
        int n = (bid - 64) * 64 + ((kt >> 3) << 5) + row;
        int src = n * Hh + k;
        float v = hclip(w_str2thal[src]);
        val = (k < (Hh / 2)) ? v : -v;
    }
    g_Wp[e] = __float2bfloat16(val);
}

// ---------------- init: hn ([b][n]) -> tiled bf16 operand (ring slot 0) --------
__global__ void init_kernel(const float* __restrict__ hn) {
    int idx = blockIdx.x * blockDim.x + threadIdx.x;
    if (idx >= Bz * H3) return;
    int b = idx / H3, n = idx - b * H3;
    int off = (n >> 7) * 4096 + b * 128 + ((((n >> 3) & 15) ^ (b & 7)) << 3) + (n & 7);
    g_hb[0][off] = __float2bfloat16(hn[idx]);
}

// ---------------- persistent tensor-core kernel ----------------------------------
__global__ void __launch_bounds__(512, 1) rnn_persist(const float* __restrict__ inp,
                                                      const float* __restrict__ iw,
                                                      const float* __restrict__ hn0,
                                                      float* __restrict__ rnn) {
    extern __shared__ __align__(256) unsigned char smem[];
    __shared__ __align__(8) unsigned long long mbar[17];   // 0..7 ringA, 8..15 ringB, 16 W

    const int tx   = threadIdx.x;
    const int bid  = blockIdx.x;
    const int wid  = tx >> 5;
    const int lane = tx & 31;
    const bool thal = (bid >= 64);

    // ---- block decode ----
    int n0, htA, htB, myTile;
    if (bid < 32)      { n0 = bid * 32;              htA = 0;  htB = 16; myTile = bid >> 2; }
    else if (bid < 64) { n0 = 2048 + (bid - 32)*32;  htA = 8;  htB = 16; myTile = 16 + ((bid - 32) >> 2); }
    else               { n0 = 1024 + (bid - 64)*64;  htA = 0;  htB = 0;  myTile = 8 + ((bid - 64) >> 1); }

    const unsigned sBase = smem_u32(smem);
    const unsigned mBase = smem_u32(mbar);

    // ---- one-time prologue: barriers + resident W (128KB) ----
    if (tx == 0) {
#pragma unroll
        for (int i = 0; i < 17; i++) mbar_init(mBase + i * 8);
    }
    __syncthreads();
    if (tx == 0) {
        mbar_expect(mBase + 16 * 8, 131072);
        bulk_cp(sBase,         g_Wp + (size_t)bid * 65536,         65536, mBase + 16 * 8);
        bulk_cp(sBase + 65536, g_Wp + (size_t)bid * 65536 + 32768, 65536, mBase + 16 * 8);
    }
    mbar_wait(mBase + 16 * 8, 0);
    __syncthreads();

    // ---- warp roles ----
    const int bt = wid & 1;
    int nh, ks, wtb;
    if (!thal) { ks = wid >> 3; nh = (wid >> 1) & 3; wtb = ks * 8; }
    else       { ks = 0;        nh = wid >> 1;       wtb = (nh >> 2) * 8; }
    const int brow = (thal ? (nh & 3) : nh) * 8 + (lane & 7);
    const bool grpB = (!thal && ks == 1);
    const unsigned ringOff = grpB ? OFF_HB : OFF_HA;
    const int barBase = grpB ? 8 : 0;
    const int slotMod = grpB ? 5 : 6;
    const int nRef    = grpB ? 3 : 2;
    const int htMine  = grpB ? htB : htA;
    const int stageTx = grpB ? 256 : 0;

    // ---- ldmatrix lane addressing ----
    const int am = lane >> 3;
    const int arow = bt * 16 + (am & 1) * 8 + (lane & 7);   // A row (batch)
    const int qa   = am >> 1;
    const int sa   = arow & 7;
    const int grp  = lane >> 3;
    const int sb   = brow & 7;
    const unsigned habase = sBase + ringOff + arow * 256;
    const unsigned wbbase = sBase + brow * 256;

    // ---- epilogue constants ----
    const int g  = lane >> 2, tg = lane & 3;
    const int pn = nh * 8 + 2 * tg;
    const int pb = bt * 16 + g;
    const int ncol = n0 + pn;
    const bool owner = thal || (ks == 0);
    float iwv[2][4];
#pragma unroll
    for (int j = 0; j < 2; j++)
#pragma unroll
        for (int i = 0; i < 4; i++) iwv[j][i] = iw[i * H3 + ncol + j];

    // ---- fp32 master h in registers (owner threads only) ----
    float hm[4];
#pragma unroll
    for (int half = 0; half < 2; half++)
#pragma unroll
        for (int j = 0; j < 2; j++)
            hm[half * 2 + j] = owner ? hn0[(pb + half * 8) * H3 + ncol + j] : 0.0f;

    // =================== time loop ===================
#pragma unroll 1
    for (int t = 0; t < Tz; t++) {
        const unsigned par = (unsigned)(t & 1);
        const __nv_bfloat16* hbc = g_hb[t & 3];
        __nv_bfloat16* hbn = g_hb[(t + 1) & 3];

        // ---- staging: warps 0..5 ring A tiles 0..5; warps 8..12 ring B 0..4 ----
        if (lane == 0) {
            if (wid < 6) {
                int tile = htA + wid;
                if (t > 0) poll_flag(&g_tflag[(t - 1) * 24 + tile], texpect(tile));
                mbar_expect(mBase + wid * 8, 8192);
                bulk_cp(sBase + OFF_HA + wid * 8192, hbc + tile * 4096, 8192, mBase + wid * 8);
            } else if (!thal && wid >= 8 && wid < 13) {
                int i = wid - 8;
                int tile = htB + i;
                if (t > 0) poll_flag(&g_tflag[(t - 1) * 24 + tile], texpect(tile));
                mbar_expect(mBase + (8 + i) * 8, 8192);
                bulk_cp(sBase + OFF_HB + i * 8192, hbc + tile * 4096, 8192, mBase + (8 + i) * 8);
            }
        }

        // ---- deferred rnn stores for step t-1 (off critical path) ----
        if (owner && t > 0) {
#pragma unroll
            for (int half = 0; half < 2; half++) {
                int b = pb + half * 8;
#pragma unroll
                for (int j = 0; j < 2; j++)
                    rnn[((size_t)(b * Tz + (t - 1))) * H3 + ncol + j] = hm[half * 2 + j];
            }
        }

        // hoist drive loads (independent of h)
        float4 iva = make_float4(0.f, 0.f, 0.f, 0.f), ivb = iva;
        if (owner) {
            iva = ((const float4*)inp)[pb * Tz + t];
            ivb = ((const float4*)inp)[(pb + 8) * Tz + t];
        }

        float d[2][4];
#pragma unroll
        for (int e = 0; e < 2; e++)
#pragma unroll
            for (int j = 0; j < 4; j++) d[e][j] = 0.f;

#pragma unroll 1
        for (int kt = 0; kt < 8; kt++) {
            mbar_wait(mBase + (barBase + kt) * 8, par);

            const unsigned ha = habase + (kt % slotMod) * 8192;
            const unsigned wa = wbbase + (wtb + kt) * 8192;
#pragma unroll
            for (int kp = 0; kp < 4; kp++) {
                unsigned b0, b1, b2, b3;
                asm volatile("ldmatrix.sync.aligned.m8n8.x4.shared.b16 {%0,%1,%2,%3}, [%4];"
                             : "=r"(b0), "=r"(b1), "=r"(b2), "=r"(b3)
                             : "r"(wa + (((4 * kp + grp) ^ sb) << 4)));
                unsigned a0, a1, a2, a3;
                asm volatile("ldmatrix.sync.aligned.m8n8.x4.shared.b16 {%0,%1,%2,%3}, [%4];"
                             : "=r"(a0), "=r"(a1), "=r"(a2), "=r"(a3)
                             : "r"(ha + (((4 * kp + qa) ^ sa) << 4)));
                asm volatile("mma.sync.aligned.m16n8k16.row.col.f32.bf16.bf16.f32 "
                             "{%0,%1,%2,%3}, {%4,%5,%6,%7}, {%8,%9}, {%0,%1,%2,%3};"
                             : "+f"(d[0][0]), "+f"(d[0][1]), "+f"(d[0][2]), "+f"(d[0][3])
                             : "r"(a0), "r"(a1), "r"(a2), "r"(a3), "r"(b0), "r"(b1));
                unsigned c0, c1, c2, c3;
                asm volatile("ldmatrix.sync.aligned.m8n8.x4.shared.b16 {%0,%1,%2,%3}, [%4];"
                             : "=r"(c0), "=r"(c1), "=r"(c2), "=r"(c3)
                             : "r"(ha + (((4 * kp + 2 + qa) ^ sa) << 4)));
                asm volatile("mma.sync.aligned.m16n8k16.row.col.f32.bf16.bf16.f32 "
                             "{%0,%1,%2,%3}, {%4,%5,%6,%7}, {%8,%9}, {%0,%1,%2,%3};"
                             : "+f"(d[1][0]), "+f"(d[1][1]), "+f"(d[1][2]), "+f"(d[1][3])
                             : "r"(c0), "r"(c1), "r"(c2), "r"(c3), "r"(b2), "r"(b3));
            }

            // group-scoped refill: tile kt+slotMod into slot kt
            if (kt < nRef) {
                if (thal) __syncthreads();
                else if (!grpB) BARS(1, 256);
                else BARS(2, 256);
                if (tx == stageTx) {
                    int i = kt + slotMod;
                    int tile = htMine + i;
                    if (t > 0) poll_flag(&g_tflag[(t - 1) * 24 + tile], texpect(tile));
                    mbar_expect(mBase + (barBase + i) * 8, 8192);
                    bulk_cp(sBase + ringOff + kt * 8192, hbc + tile * 4096, 8192,
                            mBase + (barBase + i) * 8);
                }
            }
        }

        float ds[4];
#pragma unroll
        for (int j = 0; j < 4; j++) ds[j] = d[0][j] + d[1][j];

        // ---- cross-group combine (non-thal): B writes, parity barrier, A reads ----
        if (!thal) {
            float* scb = (float*)(smem + OFF_CB) + (int)par * 1024;
            if (grpB) {
                *(float4*)&scb[(tx - 256) * 4] = make_float4(ds[0], ds[1], ds[2], ds[3]);
                if (par == 0) BARS(3, 512); else BARS(4, 512);
                // group B done: loops to t+1 staging immediately
            } else {
                if (par == 0) BARS(3, 512); else BARS(4, 512);
                const float4 p = *(const float4*)&scb[tx * 4];
                ds[0] += p.x; ds[1] += p.y; ds[2] += p.z; ds[3] += p.w;
            }
        }

        // ---- epilogue (owners): relu update in registers; write bf16 operand ----
        if (owner) {
#pragma unroll
            for (int half = 0; half < 2; half++) {
                float4 iv = half ? ivb : iva;
                float v2[2];
#pragma unroll
                for (int j = 0; j < 2; j++) {
                    float drv = iv.x * iwv[j][0] + iv.y * iwv[j][1]
                              + iv.z * iwv[j][2] + iv.w * iwv[j][3];
                    float v = fmaxf(0.9f * hm[half * 2 + j] + 0.1f * (ds[half * 2 + j] + drv), 0.0f);
                    hm[half * 2 + j] = v;
                    v2[j] = v;
                }
                int b = pb + half * 8;
                int n = ncol;
                int off = (n >> 7) * 4096 + b * 128 + ((((n >> 3) & 15) ^ (b & 7)) << 3) + (n & 7);
                __nv_bfloat162 pk;
                pk.x = __float2bfloat16(v2[0]);
                pk.y = __float2bfloat16(v2[1]);
                *(__nv_bfloat162*)&hbn[off] = pk;
            }
        }

        // ---- flag publish: owner-group barrier only ----
        if (thal) {
            __syncthreads();
            if (tx == 0) {
                __threadfence();
                atomicAdd(&g_tflag[t * 24 + myTile], 1);
            }
        } else if (!grpB) {
            BARS(1, 256);
            if (tx == 0) {
                __threadfence();
                atomicAdd(&g_tflag[t * 24 + myTile], 1);
            }
        }
    }

    // ---- drain: rnn stores for final step ----
    if (owner) {
#pragma unroll
        for (int half = 0; half < 2; half++) {
            int b = pb + half * 8;
#pragma unroll
            for (int j = 0; j < 2; j++)
                rnn[((size_t)(b * Tz + (Tz - 1))) * H3 + ncol + j] = hm[half * 2 + j];
        }
    }
}

// ---------------- heads: mean/std over masked (m1) region ----------------------
__global__ void head_kernel(const float* __restrict__ rnn,
                            const float* __restrict__ mean_w, const float* __restrict__ mean_b,
                            const float* __restrict__ std_w,  const float* __restrict__ std_b,
                            float* __restrict__ mean_out, float* __restrict__ std_out) {
    int warp = blockIdx.x * 8 + (threadIdx.x >> 5);   // = b*512 + t
    int lane = threadIdx.x & 31;
    const float* row = rnn + (size_t)warp * H3 + 2048;
    float sm = 0.0f, ss = 0.0f;
#pragma unroll 8
    for (int i = lane; i < Hh; i += 32) {
        float v = row[i];
        sm += v * mean_w[2048 + i];
        ss += v * std_w[2048 + i];
    }
#pragma unroll
    for (int off = 16; off; off >>= 1) {
        sm += __shfl_down_sync(0xFFFFFFFFu, sm, off);
        ss += __shfl_down_sync(0xFFFFFFFFu, ss, off);
    }
    if (lane == 0) {
        mean_out[warp] = sm + mean_b[0];
        float s = ss + std_b[0];
        std_out[warp] = fminf(fmaxf(s, -5.0f), 10.0f);
    }
}

// ---------------- hn_last copy --------------------------------------------------
__global__ void hn_kernel(const float* __restrict__ rnn, float* __restrict__ hn_out) {
    int idx = blockIdx.x * blockDim.x + threadIdx.x;
    if (idx >= Bz * H3) return;
    int b = idx / H3, n = idx - b * H3;
    hn_out[idx] = rnn[((size_t)(b * Tz + (Tz - 1))) * H3 + n];
}

// ---------------- launch ---------------------------------------------------------
extern "C" void kernel_launch(void* const* d_in, const int* in_sizes, int n_in,
                              void* d_out, int out_size) {
    const float* inp        = (const float*)d_in[0];   // [32,512,4]
    const float* hn         = (const float*)d_in[1];   // [1,32,3072]
    // d_in[2] = w_str2str (unused: its mask is all-zeros in the reference)
    const float* w_str2thal = (const float*)d_in[3];
    const float* w_m12m1    = (const float*)d_in[4];
    const float* w_m12str   = (const float*)d_in[5];
    const float* w_thal2m1  = (const float*)d_in[6];
    const float* fixedw     = (const float*)d_in[7];
    const float* inp_weight = (const float*)d_in[8];   // [4,3072]
    const float* mean_w     = (const float*)d_in[9];   // [1,3072]
    const float* mean_b     = (const float*)d_in[10];  // [1]
    const float* std_w      = (const float*)d_in[11];
    const float* std_b      = (const float*)d_in[12];
    // d_in[13] = sampling flag

    float* out      = (float*)d_out;
    float* mean_out = out;                         // 32*512
    float* std_out  = out + 16384;                 // 32*512
    float* hn_out   = out + 32768;                 // 32*3072
    float* rnn      = out + 131072;                // 32*512*3072

    cudaFuncSetAttribute(rnn_persist, cudaFuncAttributeMaxDynamicSharedMemorySize, SMEM_BYTES);

    prep_pack<<<(80 * 16 * 4096 + 255) / 256, 256>>>(w_str2thal, w_m12m1, w_m12str, w_thal2m1, fixedw);
    init_kernel<<<(Bz * H3 + 255) / 256, 256>>>(hn);

    rnn_persist<<<NBLK, 512, SMEM_BYTES>>>(inp, inp_weight, hn, rnn);

    head_kernel<<<2048, 256>>>(rnn, mean_w, mean_b, std_w, std_b, mean_out, std_out);
    hn_kernel<<<(Bz * H3 + 255) / 256, 256>>>(rnn, hn_out);
}

// round 16
// speedup vs baseline: 1.7251x; 1.0863x over previous
#include <cuda_runtime.h>
#include <cuda_bf16.h>
#include <cstdint>

// ---------------------------------------------------------------------------
// RNN_MultiRegional_SAC — persistent bf16 mma.sync, warp-specialized pipeline.
// h = relu(0.9 h + 0.1 (h @ W^T + drive)), 512 steps, B=32, 3H=3072.
// 80 blocks, ONE per SM, W resident in smem (128KB). 576 threads:
//   warps 0..15 compute (as R15: grpA = K-half 0 + epilogue, grpB = K-half 1),
//   warp 16 stages ring A, warp 17 stages ring B (idle for thal).
// Staging warps run a continuous producer loop over g = t*8 + kt: poll
// per-(t-1,tile) flag -> wait slot empty (parity) -> expect_tx + bulk copy.
// Compute warps: wait full -> ldmatrix/mma -> arrive empty. 4-slot rings.
// Cross-group combine via parity smem buffer + bar 3/4 (512 compute threads).
// fp32 master h in registers; rnn stores deferred one step (STG.64).
// Flags: per-(t,tile), 24 distinct addresses; depth-4 g_hb operand ring.
// Output (float32): [mean 32*512][std 32*512][hn_last 32*3072][rnn 32*512*3072]
// ---------------------------------------------------------------------------

#define Hh   1024
#define H3   3072
#define Bz   32
#define Tz   512
#define NEXC 717
#define HH   (Hh*Hh)
#define NBLK 80
#define NTHR 576

#define OFF_HA  131072u              // ring A: 4 x 8KB
#define OFF_HB  163840u              // ring B: 4 x 8KB
#define OFF_CB  196608u              // combine: 2 x 4KB (parity)
#define SMEM_BYTES 204800

// Packed, per-block-contiguous, pre-swizzled W: [bid 80][kt 16][4096 bf16] = 10.5MB
__device__ __align__(256) __nv_bfloat16 g_Wp[80u * 16u * 4096u];
// bf16 operand h, tiled+swizzled, DEPTH-4 ring: 24 tiles of 4096; tile tk holds
// k in [tk*128,(tk+1)*128): elem off = b*128 + ((((k>>3)&15)^(b&7))<<3) + (k&7)
__device__ __align__(256) __nv_bfloat16 g_hb[4][24 * 4096];
__device__ int g_tflag[Tz * 24];    // per-(step,tile) producer arrivals

// ---------------- helpers ----------------
__device__ __forceinline__ unsigned smem_u32(const void* p) {
    return (unsigned)__cvta_generic_to_shared(p);
}
__device__ __forceinline__ void bulk_cp(unsigned dstS, const void* srcG, unsigned bytes, unsigned mbarS) {
    asm volatile("cp.async.bulk.shared::cta.global.mbarrier::complete_tx::bytes [%0], [%1], %2, [%3];"
                 :: "r"(dstS), "l"(srcG), "r"(bytes), "r"(mbarS) : "memory");
}
__device__ __forceinline__ void mbar_init(unsigned mbarS, unsigned cnt) {
    asm volatile("mbarrier.init.shared.b64 [%0], %1;" :: "r"(mbarS), "r"(cnt) : "memory");
}
__device__ __forceinline__ void mbar_expect(unsigned mbarS, unsigned bytes) {
    asm volatile("mbarrier.arrive.expect_tx.shared.b64 _, [%0], %1;" :: "r"(mbarS), "r"(bytes) : "memory");
}
__device__ __forceinline__ void mbar_arrive(unsigned mbarS) {
    asm volatile("mbarrier.arrive.shared.b64 _, [%0];" :: "r"(mbarS) : "memory");
}
__device__ __forceinline__ void mbar_wait(unsigned mbarS, unsigned parity) {
    asm volatile(
        "{\n\t.reg .pred P;\n"
        "W_%=:\n\t"
        "mbarrier.try_wait.parity.acquire.cta.shared::cta.b64 P, [%0], %1, 0x989680;\n\t"
        "@P bra D_%=;\n\t"
        "bra W_%=;\n"
        "D_%=:\n\t}"
        :: "r"(mbarS), "r"(parity) : "memory");
}
__device__ __forceinline__ void poll_flag(const int* p, int expect) {
    int v;
    do {
        asm volatile("ld.acquire.gpu.global.b32 %0, [%1];" : "=r"(v) : "l"(p));
    } while (v < expect);
}
__device__ __forceinline__ int texpect(int tile) {
    return (tile < 8) ? 4 : ((tile < 16) ? 2 : 4);
}
__device__ __forceinline__ float hclip(float x) {
    return fminf(fmaxf(x, 1e-10f), 1.0f);
}
#define BARS(id, cnt) asm volatile("bar.sync " #id ", " #cnt ";" ::: "memory")

// ---------------- prep: pack W into per-block swizzled tiles + zero flags ------
__global__ void prep_pack(const float* __restrict__ w_str2thal,
                          const float* __restrict__ w_m12m1,
                          const float* __restrict__ w_m12str,
                          const float* __restrict__ w_thal2m1,
                          const float* __restrict__ fixedw) {
    int e = blockIdx.x * blockDim.x + threadIdx.x;
    if (e >= 80 * 16 * 4096) return;
    if (e < Tz * 24) g_tflag[e] = 0;

    int bid = e >> 16;              // /65536
    int rem = e & 65535;
    int kt  = rem >> 12;            // 0..15
    int wi  = rem & 4095;
    int row = wi >> 7;              // n-row within 32-row W tile
    int chunk = ((wi >> 3) & 15) ^ (row & 7);
    int kl  = (chunk << 3) | (wi & 7);
    int k   = ((kt & 7) << 7) + kl; // k within 1024-col W block

    float val;
    if (bid < 32) {                 // str: kt<8 -> W00, kt>=8 -> W02
        int n = bid * 32 + row;
        int src = n * Hh + k;
        if (kt < 8) val = -fixedw[src];
        else { float v = hclip(w_m12str[src]); val = (k < NEXC) ? v : 0.0f; }
    } else if (bid < 64) {          // m1: kt<8 -> W21, kt>=8 -> W22
        int n = (bid - 32) * 32 + row;
        int src = n * Hh + k;
        if (kt < 8) val = hclip(w_thal2m1[src]);
        else { float v = hclip(w_m12m1[src]); val = (k < NEXC) ? v : -v; }
    } else {                        // thal: 64n strip; kt<8 rows 0..31, kt>=8 rows 32..63
        int n = (bid - 64) * 64 + ((kt >> 3) << 5) + row;
        int src = n * Hh + k;
        float v = hclip(w_str2thal[src]);
        val = (k < (Hh / 2)) ? v : -v;
    }
    g_Wp[e] = __float2bfloat16(val);
}

// ---------------- init: hn ([b][n]) -> tiled bf16 operand (ring slot 0) --------
__global__ void init_kernel(const float* __restrict__ hn) {
    int idx = blockIdx.x * blockDim.x + threadIdx.x;
    if (idx >= Bz * H3) return;
    int b = idx / H3, n = idx - b * H3;
    int off = (n >> 7) * 4096 + b * 128 + ((((n >> 3) & 15) ^ (b & 7)) << 3) + (n & 7);
    g_hb[0][off] = __float2bfloat16(hn[idx]);
}

// ---------------- persistent tensor-core kernel ----------------------------------
// mbar layout: fullA 0..3, emptyA 4..7, fullB 8..11, emptyB 12..15, W 16
__global__ void __launch_bounds__(NTHR, 1) rnn_persist(const float* __restrict__ inp,
                                                       const float* __restrict__ iw,
                                                       const float* __restrict__ hn0,
                                                       float* __restrict__ rnn) {
    extern __shared__ __align__(256) unsigned char smem[];
    __shared__ __align__(8) unsigned long long mbar[17];

    const int tx   = threadIdx.x;
    const int bid  = blockIdx.x;
    const int wid  = tx >> 5;
    const int lane = tx & 31;
    const bool thal = (bid >= 64);

    // ---- block decode ----
    int n0, htA, htB, myTile;
    if (bid < 32)      { n0 = bid * 32;              htA = 0;  htB = 16; myTile = bid >> 2; }
    else if (bid < 64) { n0 = 2048 + (bid - 32)*32;  htA = 8;  htB = 16; myTile = 16 + ((bid - 32) >> 2); }
    else               { n0 = 1024 + (bid - 64)*64;  htA = 0;  htB = 0;  myTile = 8 + ((bid - 64) >> 1); }

    const unsigned sBase = smem_u32(smem);
    const unsigned mBase = smem_u32(mbar);

    // ---- one-time prologue: barriers ----
    if (tx == 0) {
        const unsigned eCntA = thal ? 16u : 8u;
#pragma unroll
        for (int i = 0; i < 4; i++) {
            mbar_init(mBase + i * 8, 1);              // fullA
            mbar_init(mBase + (4 + i) * 8, eCntA);    // emptyA
            mbar_init(mBase + (8 + i) * 8, 1);        // fullB
            mbar_init(mBase + (12 + i) * 8, 8);       // emptyB
        }
        mbar_init(mBase + 16 * 8, 1);                 // W
    }
    __syncthreads();   // all 576 threads (before any branch)

    // =================== staging warps ===================
    if (wid >= 16) {
        const bool isB = (wid == 17);
        if (lane == 0 && !(isB && thal)) {
            const int ht    = isB ? htB : htA;
            const int fBase = isB ? 8 : 0;
            const int eBase = isB ? 12 : 4;
            const unsigned ring = sBase + (isB ? OFF_HB : OFF_HA);
#pragma unroll 1
            for (int gg = 0; gg < Tz * 8; gg++) {
                int t = gg >> 3, i = gg & 7;
                int slot = gg & 3;
                unsigned epar = (unsigned)(((gg >> 2) + 1) & 1);
                int tile = ht + i;
                if (t > 0) poll_flag(&g_tflag[(t - 1) * 24 + tile], texpect(tile));
                mbar_wait(mBase + (eBase + slot) * 8, epar);
                mbar_expect(mBase + (fBase + slot) * 8, 8192);
                bulk_cp(ring + slot * 8192, g_hb[t & 3] + tile * 4096, 8192,
                        mBase + (fBase + slot) * 8);
            }
        }
        return;
    }

    // =================== compute warps ===================
    // ---- resident W load (128KB) ----
    if (tx == 0) {
        mbar_expect(mBase + 16 * 8, 131072);
        bulk_cp(sBase,         g_Wp + (size_t)bid * 65536,         65536, mBase + 16 * 8);
        bulk_cp(sBase + 65536, g_Wp + (size_t)bid * 65536 + 32768, 65536, mBase + 16 * 8);
    }
    mbar_wait(mBase + 16 * 8, 0);

    // ---- warp roles ----
    const int bt = wid & 1;
    int nh, ks, wtb;
    if (!thal) { ks = wid >> 3; nh = (wid >> 1) & 3; wtb = ks * 8; }
    else       { ks = 0;        nh = wid >> 1;       wtb = (nh >> 2) * 8; }
    const int brow = (thal ? (nh & 3) : nh) * 8 + (lane & 7);
    const bool grpB = (!thal && ks == 1);
    const unsigned ringOff = grpB ? OFF_HB : OFF_HA;
    const int fullBase  = grpB ? 8 : 0;
    const int emptyBase = grpB ? 12 : 4;

    // ---- ldmatrix lane addressing ----
    const int am = lane >> 3;
    const int arow = bt * 16 + (am & 1) * 8 + (lane & 7);   // A row (batch)
    const int qa   = am >> 1;
    const int sa   = arow & 7;
    const int grp  = lane >> 3;
    const int sb   = brow & 7;
    const unsigned habase = sBase + ringOff + arow * 256;
    const unsigned wbbase = sBase + brow * 256;

    // ---- epilogue constants ----
    const int g  = lane >> 2, tg = lane & 3;
    const int pn = nh * 8 + 2 * tg;
    const int pb = bt * 16 + g;
    const int ncol = n0 + pn;
    const bool owner = thal || (ks == 0);
    float iwv[2][4];
#pragma unroll
    for (int j = 0; j < 2; j++)
#pragma unroll
        for (int i = 0; i < 4; i++) iwv[j][i] = iw[i * H3 + ncol + j];

    // ---- fp32 master h in registers (owner threads only) ----
    float hm[4];
#pragma unroll
    for (int half = 0; half < 2; half++)
#pragma unroll
        for (int j = 0; j < 2; j++)
            hm[half * 2 + j] = owner ? hn0[(pb + half * 8) * H3 + ncol + j] : 0.0f;

    // =================== time loop ===================
#pragma unroll 1
    for (int t = 0; t < Tz; t++) {
        const unsigned par = (unsigned)(t & 1);
        __nv_bfloat16* hbn = g_hb[(t + 1) & 3];

        // ---- deferred rnn stores for step t-1 (off critical path) ----
        if (owner && t > 0) {
#pragma unroll
            for (int half = 0; half < 2; half++) {
                int b = pb + half * 8;
                *(float2*)&rnn[((size_t)(b * Tz + (t - 1))) * H3 + ncol] =
                    make_float2(hm[half * 2], hm[half * 2 + 1]);
            }
        }

        // hoist drive loads (independent of h)
        float4 iva = make_float4(0.f, 0.f, 0.f, 0.f), ivb = iva;
        if (owner) {
            iva = ((const float4*)inp)[pb * Tz + t];
            ivb = ((const float4*)inp)[(pb + 8) * Tz + t];
        }

        float d[2][4];
#pragma unroll
        for (int e = 0; e < 2; e++)
#pragma unroll
            for (int j = 0; j < 4; j++) d[e][j] = 0.f;

#pragma unroll 1
        for (int kt = 0; kt < 8; kt++) {
            const int gg = (t << 3) + kt;
            const int slot = gg & 3;
            const unsigned fpar = (unsigned)((gg >> 2) & 1);
            mbar_wait(mBase + (fullBase + slot) * 8, fpar);

            const unsigned ha = habase + slot * 8192;
            const unsigned wa = wbbase + (wtb + kt) * 8192;
#pragma unroll
            for (int kp = 0; kp < 4; kp++) {
                unsigned b0, b1, b2, b3;
                asm volatile("ldmatrix.sync.aligned.m8n8.x4.shared.b16 {%0,%1,%2,%3}, [%4];"
                             : "=r"(b0), "=r"(b1), "=r"(b2), "=r"(b3)
                             : "r"(wa + (((4 * kp + grp) ^ sb) << 4)));
                unsigned a0, a1, a2, a3;
                asm volatile("ldmatrix.sync.aligned.m8n8.x4.shared.b16 {%0,%1,%2,%3}, [%4];"
                             : "=r"(a0), "=r"(a1), "=r"(a2), "=r"(a3)
                             : "r"(ha + (((4 * kp + qa) ^ sa) << 4)));
                asm volatile("mma.sync.aligned.m16n8k16.row.col.f32.bf16.bf16.f32 "
                             "{%0,%1,%2,%3}, {%4,%5,%6,%7}, {%8,%9}, {%0,%1,%2,%3};"
                             : "+f"(d[0][0]), "+f"(d[0][1]), "+f"(d[0][2]), "+f"(d[0][3])
                             : "r"(a0), "r"(a1), "r"(a2), "r"(a3), "r"(b0), "r"(b1));
                unsigned c0, c1, c2, c3;
                asm volatile("ldmatrix.sync.aligned.m8n8.x4.shared.b16 {%0,%1,%2,%3}, [%4];"
                             : "=r"(c0), "=r"(c1), "=r"(c2), "=r"(c3)
                             : "r"(ha + (((4 * kp + 2 + qa) ^ sa) << 4)));
                asm volatile("mma.sync.aligned.m16n8k16.row.col.f32.bf16.bf16.f32 "
                             "{%0,%1,%2,%3}, {%4,%5,%6,%7}, {%8,%9}, {%0,%1,%2,%3};"
                             : "+f"(d[1][0]), "+f"(d[1][1]), "+f"(d[1][2]), "+f"(d[1][3])
                             : "r"(c0), "r"(c1), "r"(c2), "r"(c3), "r"(b2), "r"(b3));
            }

            if (lane == 0) mbar_arrive(mBase + (emptyBase + slot) * 8);
        }

        float ds[4];
#pragma unroll
        for (int j = 0; j < 4; j++) ds[j] = d[0][j] + d[1][j];

        // ---- cross-group combine (non-thal): B writes, parity barrier, A reads ----
        if (!thal) {
            float* scb = (float*)(smem + OFF_CB) + (int)par * 1024;
            if (grpB) {
                *(float4*)&scb[(tx - 256) * 4] = make_float4(ds[0], ds[1], ds[2], ds[3]);
                if (par == 0) BARS(3, 512); else BARS(4, 512);
                // group B done: loops to t+1 immediately
            } else {
                if (par == 0) BARS(3, 512); else BARS(4, 512);
                const float4 p = *(const float4*)&scb[tx * 4];
                ds[0] += p.x; ds[1] += p.y; ds[2] += p.z; ds[3] += p.w;
            }
        }

        // ---- epilogue (owners): relu update in registers; write bf16 operand ----
        if (owner) {
#pragma unroll
            for (int half = 0; half < 2; half++) {
                float4 iv = half ? ivb : iva;
                float v2[2];
#pragma unroll
                for (int j = 0; j < 2; j++) {
                    float drv = iv.x * iwv[j][0] + iv.y * iwv[j][1]
                              + iv.z * iwv[j][2] + iv.w * iwv[j][3];
                    float v = fmaxf(0.9f * hm[half * 2 + j] + 0.1f * (ds[half * 2 + j] + drv), 0.0f);
                    hm[half * 2 + j] = v;
                    v2[j] = v;
                }
                int b = pb + half * 8;
                int n = ncol;
                int off = (n >> 7) * 4096 + b * 128 + ((((n >> 3) & 15) ^ (b & 7)) << 3) + (n & 7);
                __nv_bfloat162 pk;
                pk.x = __float2bfloat16(v2[0]);
                pk.y = __float2bfloat16(v2[1]);
                *(__nv_bfloat162*)&hbn[off] = pk;
            }
        }

        // ---- flag publish: owner-group barrier only ----
        if (thal) {
            BARS(5, 512);
            if (tx == 0) {
                __threadfence();
                atomicAdd(&g_tflag[t * 24 + myTile], 1);
            }
        } else if (!grpB) {
            BARS(1, 256);
            if (tx == 0) {
                __threadfence();
                atomicAdd(&g_tflag[t * 24 + myTile], 1);
            }
        }
    }

    // ---- drain: rnn stores for final step ----
    if (owner) {
#pragma unroll
        for (int half = 0; half < 2; half++) {
            int b = pb + half * 8;
            *(float2*)&rnn[((size_t)(b * Tz + (Tz - 1))) * H3 + ncol] =
                make_float2(hm[half * 2], hm[half * 2 + 1]);
        }
    }
}

// ---------------- heads: mean/std over masked (m1) region ----------------------
__global__ void head_kernel(const float* __restrict__ rnn,
                            const float* __restrict__ mean_w, const float* __restrict__ mean_b,
                            const float* __restrict__ std_w,  const float* __restrict__ std_b,
                            float* __restrict__ mean_out, float* __restrict__ std_out) {
    int warp = blockIdx.x * 8 + (threadIdx.x >> 5);   // = b*512 + t
    int lane = threadIdx.x & 31;
    const float* row = rnn + (size_t)warp * H3 + 2048;
    float sm = 0.0f, ss = 0.0f;
#pragma unroll 8
    for (int i = lane; i < Hh; i += 32) {
        float v = row[i];
        sm += v * mean_w[2048 + i];
        ss += v * std_w[2048 + i];
    }
#pragma unroll
    for (int off = 16; off; off >>= 1) {
        sm += __shfl_down_sync(0xFFFFFFFFu, sm, off);
        ss += __shfl_down_sync(0xFFFFFFFFu, ss, off);
    }
    if (lane == 0) {
        mean_out[warp] = sm + mean_b[0];
        float s = ss + std_b[0];
        std_out[warp] = fminf(fmaxf(s, -5.0f), 10.0f);
    }
}

// ---------------- hn_last copy --------------------------------------------------
__global__ void hn_kernel(const float* __restrict__ rnn, float* __restrict__ hn_out) {
    int idx = blockIdx.x * blockDim.x + threadIdx.x;
    if (idx >= Bz * H3) return;
    int b = idx / H3, n = idx - b * H3;
    hn_out[idx] = rnn[((size_t)(b * Tz + (Tz - 1))) * H3 + n];
}

// ---------------- launch ---------------------------------------------------------
extern "C" void kernel_launch(void* const* d_in, const int* in_sizes, int n_in,
                              void* d_out, int out_size) {
    const float* inp        = (const float*)d_in[0];   // [32,512,4]
    const float* hn         = (const float*)d_in[1];   // [1,32,3072]
    // d_in[2] = w_str2str (unused: its mask is all-zeros in the reference)
    const float* w_str2thal = (const float*)d_in[3];
    const float* w_m12m1    = (const float*)d_in[4];
    const float* w_m12str   = (const float*)d_in[5];
    const float* w_thal2m1  = (const float*)d_in[6];
    const float* fixedw     = (const float*)d_in[7];
    const float* inp_weight = (const float*)d_in[8];   // [4,3072]
    const float* mean_w     = (const float*)d_in[9];   // [1,3072]
    const float* mean_b     = (const float*)d_in[10];  // [1]
    const float* std_w      = (const float*)d_in[11];
    const float* std_b      = (const float*)d_in[12];
    // d_in[13] = sampling flag

    float* out      = (float*)d_out;
    float* mean_out = out;                         // 32*512
    float* std_out  = out + 16384;                 // 32*512
    float* hn_out   = out + 32768;                 // 32*3072
    float* rnn      = out + 131072;                // 32*512*3072

    cudaFuncSetAttribute(rnn_persist, cudaFuncAttributeMaxDynamicSharedMemorySize, SMEM_BYTES);

    prep_pack<<<(80 * 16 * 4096 + 255) / 256, 256>>>(w_str2thal, w_m12m1, w_m12str, w_thal2m1, fixedw);
    init_kernel<<<(Bz * H3 + 255) / 256, 256>>>(hn);

    rnn_persist<<<NBLK, NTHR, SMEM_BYTES>>>(inp, inp_weight, hn, rnn);

    head_kernel<<<2048, 256>>>(rnn, mean_w, mean_b, std_w, std_b, mean_out, std_out);
    hn_kernel<<<(Bz * H3 + 255) / 256, 256>>>(rnn, hn_out);
}